// round 13
// baseline (speedup 1.0000x reference)
#include <cuda_runtime.h>
#include <cuda_fp16.h>
#include <cstdint>

// Problem constants
#define B_   16
#define NP_  4096
#define NT_  77
#define QD_  512
#define CD_  768
#define H_   8
#define DH_  64
#define INNER_ 512   // H*DH

// ---------------------------------------------------------------------------
// Scratch (device globals)
// ---------------------------------------------------------------------------
__device__ __half    g_Qh [(size_t)B_ * NP_ * INNER_];
__device__ __half    g_Kh [(size_t)B_ * NT_ * INNER_];
__device__ __half    g_Vh [(size_t)B_ * NT_ * INNER_];
__device__ __half    g_xh [(size_t)B_ * NP_ * QD_];
__device__ __half    g_ah [(size_t)B_ * NP_ * INNER_];
__device__ __half    g_ch [(size_t)B_ * NT_ * CD_];
__device__ __half    g_WqT[(size_t)QD_ * INNER_];
__device__ __half    g_WkT[(size_t)CD_ * INNER_];
__device__ __half    g_WvT[(size_t)CD_ * INNER_];
__device__ __half    g_WoT[(size_t)INNER_ * QD_];
__device__ uint32_t  g_mb [(size_t)B_ * NP_ * 4];

// ---------------------------------------------------------------------------
// PTX helpers
// ---------------------------------------------------------------------------
__device__ __forceinline__ uint32_t smem_u32(const void* p) {
    uint32_t a;
    asm("{ .reg .u64 t; cvta.to.shared.u64 t, %1; cvt.u32.u64 %0, t; }" : "=r"(a) : "l"(p));
    return a;
}

#define LDSM_X4(r0, r1, r2, r3, addr) \
    asm volatile("ldmatrix.sync.aligned.m8n8.x4.shared.b16 {%0,%1,%2,%3}, [%4];" \
        : "=r"(r0), "=r"(r1), "=r"(r2), "=r"(r3) : "r"(addr))

#define MMA_F16(c0, c1, c2, c3, a0, a1, a2, a3, b0, b1) \
    asm volatile("mma.sync.aligned.m16n8k16.row.col.f32.f16.f16.f32 " \
        "{%0,%1,%2,%3}, {%4,%5,%6,%7}, {%8,%9}, {%0,%1,%2,%3};" \
        : "+f"(c0), "+f"(c1), "+f"(c2), "+f"(c3) \
        : "r"(a0), "r"(a1), "r"(a2), "r"(a3), "r"(b0), "r"(b1))

#define CP_ASYNC16(dst, src) \
    asm volatile("cp.async.cg.shared.global [%0], [%1], 16;" :: "r"(dst), "l"(src))
#define CP_COMMIT() asm volatile("cp.async.commit_group;" ::: "memory")
#define CP_WAIT0()  asm volatile("cp.async.wait_group 0;" ::: "memory")

// BK=64 smem tile: rows of 64 halves (128B); 16B chunks XOR-swizzled.
__device__ __forceinline__ uint32_t tile_off64(int row, int chunk) {
    return (uint32_t)(row * 128 + ((chunk ^ (row & 7)) << 4));
}

__device__ __forceinline__ uint32_t packh2(float x, float y) {
    __half2 h = __floats2half2_rn(x, y);
    return *reinterpret_cast<uint32_t*>(&h);
}

// ---------------------------------------------------------------------------
// Mega prep kernel (unchanged)
// ---------------------------------------------------------------------------
#define PX_N4   ((B_ * NP_ * QD_) / 4)
#define PC_N4   ((B_ * NT_ * CD_) / 4)
#define PX_BLK  (PX_N4 / 256)
#define PC_BLK  (PC_N4 / 256)
#define WQ_BLK  ((QD_ / 32) * (INNER_ / 32))
#define WK_BLK  ((CD_ / 32) * (INNER_ / 32))
#define WV_BLK  WK_BLK
#define WO_BLK  ((INNER_ / 32) * (QD_ / 32))
#define MB_BLK  ((B_ * NP_) / 8)

#define E_X   PX_BLK
#define E_C   (E_X + PC_BLK)
#define E_WQ  (E_C + WQ_BLK)
#define E_WK  (E_WQ + WK_BLK)
#define E_WV  (E_WK + WV_BLK)
#define E_WO  (E_WV + WO_BLK)
#define E_MB  (E_WO + MB_BLK)
#define PREP_BLOCKS E_MB

__device__ __forceinline__ void tohalf_sub(const float4* in, __half2* out, int i)
{
    float4 v = in[i];
    out[2 * i]     = __floats2half2_rn(v.x, v.y);
    out[2 * i + 1] = __floats2half2_rn(v.z, v.w);
}

__device__ __forceinline__ void transT_sub(const float* in, __half* out,
                                           int K, int N, int t, int tid,
                                           float (*tsm)[33])
{
    const int ktiles = K / 32;
    const int kb = (t % ktiles) * 32;
    const int nb = (t / ktiles) * 32;
    const int tx = tid & 31;
    const int ty = tid >> 5;
    #pragma unroll
    for (int i = 0; i < 32; i += 8)
        tsm[ty + i][tx] = in[(size_t)(kb + ty + i) * N + nb + tx];
    __syncthreads();
    #pragma unroll
    for (int i = 0; i < 32; i += 8)
        out[(size_t)(nb + ty + i) * K + kb + tx] = __float2half_rn(tsm[tx][ty + i]);
}

__global__ __launch_bounds__(256)
void prep_kernel(const float* __restrict__ x, const float* __restrict__ ctx,
                 const int* __restrict__ mask,
                 const float* __restrict__ Wq, const float* __restrict__ Wk,
                 const float* __restrict__ Wv, const float* __restrict__ Wo,
                 __half* __restrict__ xh, __half* __restrict__ ch,
                 __half* __restrict__ wqt, __half* __restrict__ wkt,
                 __half* __restrict__ wvt, __half* __restrict__ wot,
                 uint32_t* __restrict__ mbits)
{
    __shared__ float tsm[32][33];
    const int bid = blockIdx.x;
    const int tid = threadIdx.x;

    if (bid < E_X) {
        tohalf_sub((const float4*)x, (__half2*)xh, bid * 256 + tid);
    } else if (bid < E_C) {
        tohalf_sub((const float4*)ctx, (__half2*)ch, (bid - E_X) * 256 + tid);
    } else if (bid < E_WQ) {
        transT_sub(Wq, wqt, QD_, INNER_, bid - E_C, tid, tsm);
    } else if (bid < E_WK) {
        transT_sub(Wk, wkt, CD_, INNER_, bid - E_WQ, tid, tsm);
    } else if (bid < E_WV) {
        transT_sub(Wv, wvt, CD_, INNER_, bid - E_WK, tid, tsm);
    } else if (bid < E_WO) {
        transT_sub(Wo, wot, INNER_, QD_, bid - E_WV, tid, tsm);
    } else {
        const int w = (bid - E_WO) * 8 + (tid >> 5);
        const int lane = tid & 31;
        const int* row = mask + (size_t)w * NT_;
        uint32_t b0 = __ballot_sync(0xFFFFFFFF, row[lane] != 0);
        uint32_t b1 = __ballot_sync(0xFFFFFFFF, row[32 + lane] != 0);
        uint32_t b2 = __ballot_sync(0xFFFFFFFF, (64 + lane < NT_) ? (row[64 + lane] != 0) : 0);
        if (lane == 0) {
            mbits[(size_t)w * 4 + 0] = b0;
            mbits[(size_t)w * 4 + 1] = b1;
            mbits[(size_t)w * 4 + 2] = b2;
            mbits[(size_t)w * 4 + 3] = 0;
        }
    }
}

// ---------------------------------------------------------------------------
// GEMM core: 128x128 CTA tile, 4 warps (128 thr) of 64x64 warp tiles (2x2),
// BK=64, 2-stage cp.async double buffer, KVAL compile-time (full unroll).
// LDSM:HMMA ratio 4.0 (vs 2.67 of the 8-warp 64x32 layout) -> 1.5x less
// shared traffic per MMA. 3 CTAs/SM (reg-capped by __launch_bounds__(128,3)).
// ---------------------------------------------------------------------------
#define STG_A 0
#define STG_B 16384
#define STG_SIZE 32768
#define PIPE_SMEM (2 * STG_SIZE)   // 65536

#define QY 512
#define KVY 10

template<int KVAL, bool GUARD>
__device__ __forceinline__ void gemm_core(
    const __half* __restrict__ A, const __half* __restrict__ BT,
    float c[4][8][4], uint32_t smem_base,
    int m0, int n0, int M, int tid,
    int warp_m, int warp_n, int lrow, int lchk)
{
    constexpr int NCH = KVAL >> 6;

    auto load_chunk = [&](int s, int k0) {
        const uint32_t sb = smem_base + s * STG_SIZE;
        #pragma unroll
        for (int t = 0; t < 8; t++) {
            const int idx = tid + t * 128;
            const int row = idx >> 3, cc = idx & 7;
            const int ar = GUARD ? min(m0 + row, M - 1) : (m0 + row);
            CP_ASYNC16(sb + STG_A + tile_off64(row, cc),
                       A + (size_t)ar * KVAL + k0 + cc * 8);
        }
        #pragma unroll
        for (int t = 0; t < 8; t++) {
            const int idx = tid + t * 128;
            const int row = idx >> 3, cc = idx & 7;
            CP_ASYNC16(sb + STG_B + tile_off64(row, cc),
                       BT + (size_t)(n0 + row) * KVAL + k0 + cc * 8);
        }
        CP_COMMIT();
    };

    load_chunk(0, 0);

    #pragma unroll
    for (int ch_ = 0; ch_ < NCH; ch_++) {
        CP_WAIT0();                 // chunk ch_ landed (it is the only pending group)
        __syncthreads();
        if (ch_ + 1 < NCH)
            load_chunk((ch_ + 1) & 1, (ch_ + 1) << 6);

        const uint32_t sb = smem_base + (ch_ & 1) * STG_SIZE;

        #pragma unroll
        for (int ks = 0; ks < 4; ks++) {
            const int kc = ks * 2;
            uint32_t b[8][2];
            #pragma unroll
            for (int fp = 0; fp < 4; fp++) {
                const int row = warp_n * 64 + fp * 16 + lrow;
                uint32_t r0, r1, r2, r3;
                LDSM_X4(r0, r1, r2, r3, sb + STG_B + tile_off64(row, kc + lchk));
                b[2 * fp + 0][0] = r0; b[2 * fp + 0][1] = r2;
                b[2 * fp + 1][0] = r1; b[2 * fp + 1][1] = r3;
            }
            #pragma unroll
            for (int fm = 0; fm < 4; fm++) {
                const int row = warp_m * 64 + fm * 16 + lrow;
                uint32_t a0, a1, a2, a3;
                LDSM_X4(a0, a1, a2, a3, sb + STG_A + tile_off64(row, kc + lchk));
                #pragma unroll
                for (int fn = 0; fn < 8; fn++)
                    MMA_F16(c[fm][fn][0], c[fm][fn][1], c[fm][fn][2], c[fm][fn][3],
                            a0, a1, a2, a3, b[fn][0], b[fn][1]);
            }
        }
        __syncthreads();            // all warps done with stage before reuse
    }
}

// ---------------------------------------------------------------------------
// Merged Q/K/V projection GEMM (one launch).
// ---------------------------------------------------------------------------
__global__ __launch_bounds__(128, 3)
void qkv_gemm_pipe(const __half* __restrict__ xh, const __half* __restrict__ wqt,
                   __half* __restrict__ Qh,
                   const __half* __restrict__ ch, const __half* __restrict__ wkt,
                   __half* __restrict__ Kh, const __half* __restrict__ wvt,
                   __half* __restrict__ Vh)
{
    extern __shared__ __align__(1024) char dsm[];
    const uint32_t smem_base = smem_u32(dsm);

    const int by = blockIdx.y;
    const int tid  = threadIdx.x;
    const int wid  = tid >> 5;
    const int lane = tid & 31;
    const int warp_m = wid >> 1;   // 0..1
    const int warp_n = wid & 1;    // 0..1
    const int n0 = blockIdx.x * 128;
    const int N = INNER_;

    float c[4][8][4];
    #pragma unroll
    for (int i = 0; i < 4; i++)
        #pragma unroll
        for (int j = 0; j < 8; j++)
            #pragma unroll
            for (int r = 0; r < 4; r++) c[i][j][r] = 0.f;

    const int lrow = lane & 15;
    const int lchk = lane >> 4;

    __half* C;
    int M, m0;
    bool guard;
    if (by < QY) {
        M = B_ * NP_; m0 = by * 128; C = Qh; guard = false;
        gemm_core<QD_, false>(xh, wqt, c, smem_base, m0, n0, M, tid,
                              warp_m, warp_n, lrow, lchk);
    } else {
        M = B_ * NT_;
        const __half* BT;
        if (by < QY + KVY) { m0 = (by - QY) * 128; BT = wkt; C = Kh; }
        else               { m0 = (by - QY - KVY) * 128; BT = wvt; C = Vh; }
        guard = true;
        gemm_core<CD_, true>(ch, BT, c, smem_base, m0, n0, M, tid,
                             warp_m, warp_n, lrow, lchk);
    }

    #pragma unroll
    for (int fm = 0; fm < 4; fm++) {
        const int r0 = m0 + warp_m * 64 + fm * 16 + (lane >> 2);
        #pragma unroll
        for (int fn = 0; fn < 8; fn++) {
            const int col = n0 + warp_n * 64 + fn * 8 + (lane & 3) * 2;
            if (!guard || r0 < M)
                *reinterpret_cast<__half2*>(C + (size_t)r0 * N + col) =
                    __floats2half2_rn(c[fm][fn][0], c[fm][fn][1]);
            if (!guard || r0 + 8 < M)
                *reinterpret_cast<__half2*>(C + (size_t)(r0 + 8) * N + col) =
                    __floats2half2_rn(c[fm][fn][2], c[fm][fn][3]);
        }
    }
}

// ---------------------------------------------------------------------------
// O-projection GEMM (fp32 out + bias, M%128==0, K=INNER_ compile-time).
// ---------------------------------------------------------------------------
__global__ __launch_bounds__(128, 3)
void o_gemm_pipe(const __half* __restrict__ A, const __half* __restrict__ BT,
                 float* __restrict__ C, const float* __restrict__ bias)
{
    extern __shared__ __align__(1024) char dsm[];
    const uint32_t smem_base = smem_u32(dsm);

    const int tid  = threadIdx.x;
    const int wid  = tid >> 5;
    const int lane = tid & 31;
    const int warp_m = wid >> 1;
    const int warp_n = wid & 1;
    const int m0 = blockIdx.y * 128;
    const int n0 = blockIdx.x * 128;
    const int N = QD_;

    float c[4][8][4];
    #pragma unroll
    for (int i = 0; i < 4; i++)
        #pragma unroll
        for (int j = 0; j < 8; j++)
            #pragma unroll
            for (int r = 0; r < 4; r++) c[i][j][r] = 0.f;

    const int lrow = lane & 15;
    const int lchk = lane >> 4;

    gemm_core<INNER_, false>(A, BT, c, smem_base, m0, n0, B_ * NP_, tid,
                             warp_m, warp_n, lrow, lchk);

    #pragma unroll
    for (int fm = 0; fm < 4; fm++) {
        const int r0 = m0 + warp_m * 64 + fm * 16 + (lane >> 2);
        #pragma unroll
        for (int fn = 0; fn < 8; fn++) {
            const int col = n0 + warp_n * 64 + fn * 8 + (lane & 3) * 2;
            const float bx = bias[col], by = bias[col + 1];
            *reinterpret_cast<float2*>(C + (size_t)r0 * N + col) =
                make_float2(c[fm][fn][0] + bx, c[fm][fn][1] + by);
            *reinterpret_cast<float2*>(C + (size_t)(r0 + 8) * N + col) =
                make_float2(c[fm][fn][2] + bx, c[fm][fn][3] + by);
        }
    }
}

// ---------------------------------------------------------------------------
// Tensor-core flash attention; mask via precomputed bitwords. (unchanged)
// ---------------------------------------------------------------------------
#define NTP 80
#define QS_PITCH 72
#define VT_PITCH 88

__global__ __launch_bounds__(256)
void fattn_kernel(const __half* __restrict__ Qh, const __half* __restrict__ Kh,
                  const __half* __restrict__ Vh, const uint32_t* __restrict__ mbits,
                  __half* __restrict__ Oh)
{
    __shared__ __half Qs[128 * QS_PITCH];
    __shared__ __half Ks[NTP * QS_PITCH];
    __shared__ __half Vt[DH_ * VT_PITCH];

    const int b = blockIdx.z;
    const int h = blockIdx.y;
    const int q0 = blockIdx.x * 128;
    const int tid = threadIdx.x;
    const int wid = tid >> 5;
    const int lane = tid & 31;

    const uint32_t qs = smem_u32(Qs);
    const uint32_t ks = smem_u32(Ks);
    const uint32_t vt = smem_u32(Vt);

    #pragma unroll
    for (int t = 0; t < 4; t++) {
        const int idx = tid + t * 256;
        const int row = idx >> 3, cc = idx & 7;
        CP_ASYNC16(qs + (row * QS_PITCH + cc * 8) * 2,
                   Qh + ((size_t)(b * NP_ + q0 + row)) * INNER_ + h * DH_ + cc * 8);
    }
    for (int idx = tid; idx < NT_ * 8; idx += 256) {
        const int row = idx >> 3, cc = idx & 7;
        CP_ASYNC16(ks + (row * QS_PITCH + cc * 8) * 2,
                   Kh + ((size_t)(b * NT_ + row)) * INNER_ + h * DH_ + cc * 8);
    }
    CP_COMMIT();

    for (int i = tid; i < 3 * QS_PITCH; i += 256)
        Ks[NT_ * QS_PITCH + i] = __float2half(0.f);
    for (int i = tid; i < DH_ * VT_PITCH / 2; i += 256)
        reinterpret_cast<__half2*>(Vt)[i] = __half2(__float2half(0.f), __float2half(0.f));
    __syncthreads();

    for (int idx = tid; idx < NT_ * DH_; idx += 256) {
        const int t = idx >> 6, d = idx & 63;
        Vt[d * VT_PITCH + t] = Vh[((size_t)(b * NT_ + t)) * INNER_ + h * DH_ + d];
    }
    CP_WAIT0();
    __syncthreads();

    const int lrow = lane & 15;
    const int lchk = lane >> 4;

    float s[10][4];
    #pragma unroll
    for (int f = 0; f < 10; f++)
        #pragma unroll
        for (int r = 0; r < 4; r++) s[f][r] = 0.f;

    #pragma unroll
    for (int kstep = 0; kstep < 4; kstep++) {
        const int kc = kstep * 2;
        uint32_t a0, a1, a2, a3;
        LDSM_X4(a0, a1, a2, a3,
                qs + ((wid * 16 + lrow) * QS_PITCH + (kc + lchk) * 8) * 2);
        #pragma unroll
        for (int g = 0; g < 5; g++) {
            uint32_t r0, r1, r2, r3;
            LDSM_X4(r0, r1, r2, r3,
                    ks + ((g * 16 + lrow) * QS_PITCH + (kc + lchk) * 8) * 2);
            MMA_F16(s[2*g+0][0], s[2*g+0][1], s[2*g+0][2], s[2*g+0][3],
                    a0, a1, a2, a3, r0, r2);
            MMA_F16(s[2*g+1][0], s[2*g+1][1], s[2*g+1][2], s[2*g+1][3],
                    a0, a1, a2, a3, r1, r3);
        }
    }

    const int ra = q0 + wid * 16 + (lane >> 2);
    const int rb = ra + 8;
    const uint32_t* bA = mbits + (size_t)(b * NP_ + ra) * 4;
    const uint32_t* bB = mbits + (size_t)(b * NP_ + rb) * 4;
    const uint32_t a0w = bA[0], a1w = bA[1], a2w = bA[2];
    const uint32_t b0w = bB[0], b1w = bB[1], b2w = bB[2];

    float suma = 0.f, sumb = 0.f;
    #pragma unroll
    for (int f = 0; f < 10; f++) {
        const int t0 = f * 8 + (lane & 3) * 2;
        const uint32_t wa = (f < 4) ? a0w : (f < 8) ? a1w : a2w;
        const uint32_t wb = (f < 4) ? b0w : (f < 8) ? b1w : b2w;
        const int sh = t0 & 31;
        float e0 = ((wa >> sh) & 1)       ? __expf(s[f][0] * 0.125f) : 0.f;
        float e1 = ((wa >> (sh + 1)) & 1) ? __expf(s[f][1] * 0.125f) : 0.f;
        float e2 = ((wb >> sh) & 1)       ? __expf(s[f][2] * 0.125f) : 0.f;
        float e3 = ((wb >> (sh + 1)) & 1) ? __expf(s[f][3] * 0.125f) : 0.f;
        s[f][0] = e0; s[f][1] = e1; s[f][2] = e2; s[f][3] = e3;
        suma += e0 + e1;
        sumb += e2 + e3;
    }
    suma += __shfl_xor_sync(0xFFFFFFFF, suma, 1);
    suma += __shfl_xor_sync(0xFFFFFFFF, suma, 2);
    sumb += __shfl_xor_sync(0xFFFFFFFF, sumb, 1);
    sumb += __shfl_xor_sync(0xFFFFFFFF, sumb, 2);
    const float inva = 1.f / suma;
    const float invb = 1.f / sumb;

    uint32_t p[5][4];
    #pragma unroll
    for (int kstep = 0; kstep < 5; kstep++) {
        const int f0 = 2 * kstep, f1 = 2 * kstep + 1;
        p[kstep][0] = packh2(s[f0][0], s[f0][1]);
        p[kstep][1] = packh2(s[f0][2], s[f0][3]);
        p[kstep][2] = packh2(s[f1][0], s[f1][1]);
        p[kstep][3] = packh2(s[f1][2], s[f1][3]);
    }

    float o[8][4];
    #pragma unroll
    for (int f = 0; f < 8; f++)
        #pragma unroll
        for (int r = 0; r < 4; r++) o[f][r] = 0.f;

    #pragma unroll
    for (int kstep = 0; kstep < 5; kstep++) {
        const int tc = kstep * 2;
        #pragma unroll
        for (int g = 0; g < 4; g++) {
            uint32_t r0, r1, r2, r3;
            LDSM_X4(r0, r1, r2, r3,
                    vt + ((g * 16 + lrow) * VT_PITCH + (tc + lchk) * 8) * 2);
            MMA_F16(o[2*g+0][0], o[2*g+0][1], o[2*g+0][2], o[2*g+0][3],
                    p[kstep][0], p[kstep][1], p[kstep][2], p[kstep][3], r0, r2);
            MMA_F16(o[2*g+1][0], o[2*g+1][1], o[2*g+1][2], o[2*g+1][3],
                    p[kstep][0], p[kstep][1], p[kstep][2], p[kstep][3], r1, r3);
        }
    }

    __half* outA = Oh + ((size_t)(b * NP_ + ra)) * INNER_ + h * DH_;
    __half* outB = Oh + ((size_t)(b * NP_ + rb)) * INNER_ + h * DH_;
    #pragma unroll
    for (int f = 0; f < 8; f++) {
        const int d = f * 8 + (lane & 3) * 2;
        *reinterpret_cast<__half2*>(outA + d) =
            __floats2half2_rn(o[f][0] * inva, o[f][1] * inva);
        *reinterpret_cast<__half2*>(outB + d) =
            __floats2half2_rn(o[f][2] * invb, o[f][3] * invb);
    }
}

// ---------------------------------------------------------------------------
// Launch: 4 kernels total.
// ---------------------------------------------------------------------------
extern "C" void kernel_launch(void* const* d_in, const int* in_sizes, int n_in,
                              void* d_out, int out_size)
{
    const float* x    = (const float*)d_in[0];
    const float* ctx  = (const float*)d_in[1];
    const int*   mask = (const int*)  d_in[2];
    const float* Wq   = (const float*)d_in[3];
    const float* Wk   = (const float*)d_in[4];
    const float* Wv   = (const float*)d_in[5];
    const float* Wo   = (const float*)d_in[6];
    const float* bo   = (const float*)d_in[7];
    float* out = (float*)d_out;

    __half *Qh, *Kh, *Vh, *xh, *ah, *ch, *wqt, *wkt, *wvt, *wot;
    uint32_t* mb;
    cudaGetSymbolAddress((void**)&Qh,  g_Qh);
    cudaGetSymbolAddress((void**)&Kh,  g_Kh);
    cudaGetSymbolAddress((void**)&Vh,  g_Vh);
    cudaGetSymbolAddress((void**)&xh,  g_xh);
    cudaGetSymbolAddress((void**)&ah,  g_ah);
    cudaGetSymbolAddress((void**)&ch,  g_ch);
    cudaGetSymbolAddress((void**)&wqt, g_WqT);
    cudaGetSymbolAddress((void**)&wkt, g_WkT);
    cudaGetSymbolAddress((void**)&wvt, g_WvT);
    cudaGetSymbolAddress((void**)&wot, g_WoT);
    cudaGetSymbolAddress((void**)&mb,  g_mb);

    cudaFuncSetAttribute(qkv_gemm_pipe,
                         cudaFuncAttributeMaxDynamicSharedMemorySize, PIPE_SMEM);
    cudaFuncSetAttribute(o_gemm_pipe,
                         cudaFuncAttributeMaxDynamicSharedMemorySize, PIPE_SMEM);

    const int Mq = B_ * NP_;   // 65536

    // 1) all conversions + mask bits, one launch
    prep_kernel<<<PREP_BLOCKS, 256>>>(x, ctx, mask, Wq, Wk, Wv, Wo,
                                      xh, ch, wqt, wkt, wvt, wot, mb);

    // 2) Q + K + V projections, one launch
    qkv_gemm_pipe<<<dim3(INNER_ / 128, QY + 2 * KVY, 1), 128, PIPE_SMEM>>>(
        xh, wqt, Qh, ch, wkt, Kh, wvt, Vh);

    // 3) tensor-core flash attention -> fp16
    fattn_kernel<<<dim3(NP_ / 128, H_, B_), 256>>>(Qh, Kh, Vh, mb, ah);

    // 4) out = Att @ Wo + bo
    o_gemm_pipe<<<dim3(QD_ / 128, Mq / 128, 1), 128, PIPE_SMEM>>>(
        ah, wot, out, bo);
}

// round 14
// speedup vs baseline: 1.2815x; 1.2815x over previous
#include <cuda_runtime.h>
#include <cuda_fp16.h>
#include <cstdint>

// Problem constants
#define B_   16
#define NP_  4096
#define NT_  77
#define QD_  512
#define CD_  768
#define H_   8
#define DH_  64
#define INNER_ 512   // H*DH

// ---------------------------------------------------------------------------
// Scratch (device globals)
// ---------------------------------------------------------------------------
__device__ __half    g_Qh [(size_t)B_ * NP_ * INNER_];
__device__ __half    g_Kh [(size_t)B_ * NT_ * INNER_];
__device__ __half    g_Vh [(size_t)B_ * NT_ * INNER_];
__device__ __half    g_xh [(size_t)B_ * NP_ * QD_];
__device__ __half    g_ah [(size_t)B_ * NP_ * INNER_];
__device__ __half    g_ch [(size_t)B_ * NT_ * CD_];
__device__ __half    g_WqT[(size_t)QD_ * INNER_];
__device__ __half    g_WkT[(size_t)CD_ * INNER_];
__device__ __half    g_WvT[(size_t)CD_ * INNER_];
__device__ __half    g_WoT[(size_t)INNER_ * QD_];
__device__ uint32_t  g_mb [(size_t)B_ * NP_ * 4];

// ---------------------------------------------------------------------------
// PTX helpers
// ---------------------------------------------------------------------------
__device__ __forceinline__ uint32_t smem_u32(const void* p) {
    uint32_t a;
    asm("{ .reg .u64 t; cvta.to.shared.u64 t, %1; cvt.u32.u64 %0, t; }" : "=r"(a) : "l"(p));
    return a;
}

#define LDSM_X4(r0, r1, r2, r3, addr) \
    asm volatile("ldmatrix.sync.aligned.m8n8.x4.shared.b16 {%0,%1,%2,%3}, [%4];" \
        : "=r"(r0), "=r"(r1), "=r"(r2), "=r"(r3) : "r"(addr))

#define MMA_F16(c0, c1, c2, c3, a0, a1, a2, a3, b0, b1) \
    asm volatile("mma.sync.aligned.m16n8k16.row.col.f32.f16.f16.f32 " \
        "{%0,%1,%2,%3}, {%4,%5,%6,%7}, {%8,%9}, {%0,%1,%2,%3};" \
        : "+f"(c0), "+f"(c1), "+f"(c2), "+f"(c3) \
        : "r"(a0), "r"(a1), "r"(a2), "r"(a3), "r"(b0), "r"(b1))

#define CP_ASYNC16(dst, src) \
    asm volatile("cp.async.cg.shared.global [%0], [%1], 16;" :: "r"(dst), "l"(src))
#define CP_COMMIT() asm volatile("cp.async.commit_group;" ::: "memory")
#define CP_WAIT1()  asm volatile("cp.async.wait_group 1;" ::: "memory")
#define CP_WAIT0()  asm volatile("cp.async.wait_group 0;" ::: "memory")

// BK=64 smem tile: rows of 64 halves (128B); 16B chunks XOR-swizzled.
__device__ __forceinline__ uint32_t tile_off64(int row, int chunk) {
    return (uint32_t)(row * 128 + ((chunk ^ (row & 7)) << 4));
}

__device__ __forceinline__ uint32_t packh2(float x, float y) {
    __half2 h = __floats2half2_rn(x, y);
    return *reinterpret_cast<uint32_t*>(&h);
}

// ---------------------------------------------------------------------------
// Mega prep kernel (unchanged)
// ---------------------------------------------------------------------------
#define PX_N4   ((B_ * NP_ * QD_) / 4)
#define PC_N4   ((B_ * NT_ * CD_) / 4)
#define PX_BLK  (PX_N4 / 256)
#define PC_BLK  (PC_N4 / 256)
#define WQ_BLK  ((QD_ / 32) * (INNER_ / 32))
#define WK_BLK  ((CD_ / 32) * (INNER_ / 32))
#define WV_BLK  WK_BLK
#define WO_BLK  ((INNER_ / 32) * (QD_ / 32))
#define MB_BLK  ((B_ * NP_) / 8)

#define E_X   PX_BLK
#define E_C   (E_X + PC_BLK)
#define E_WQ  (E_C + WQ_BLK)
#define E_WK  (E_WQ + WK_BLK)
#define E_WV  (E_WK + WV_BLK)
#define E_WO  (E_WV + WO_BLK)
#define E_MB  (E_WO + MB_BLK)
#define PREP_BLOCKS E_MB

__device__ __forceinline__ void tohalf_sub(const float4* in, __half2* out, int i)
{
    float4 v = in[i];
    out[2 * i]     = __floats2half2_rn(v.x, v.y);
    out[2 * i + 1] = __floats2half2_rn(v.z, v.w);
}

__device__ __forceinline__ void transT_sub(const float* in, __half* out,
                                           int K, int N, int t, int tid,
                                           float (*tsm)[33])
{
    const int ktiles = K / 32;
    const int kb = (t % ktiles) * 32;
    const int nb = (t / ktiles) * 32;
    const int tx = tid & 31;
    const int ty = tid >> 5;
    #pragma unroll
    for (int i = 0; i < 32; i += 8)
        tsm[ty + i][tx] = in[(size_t)(kb + ty + i) * N + nb + tx];
    __syncthreads();
    #pragma unroll
    for (int i = 0; i < 32; i += 8)
        out[(size_t)(nb + ty + i) * K + kb + tx] = __float2half_rn(tsm[tx][ty + i]);
}

__global__ __launch_bounds__(256)
void prep_kernel(const float* __restrict__ x, const float* __restrict__ ctx,
                 const int* __restrict__ mask,
                 const float* __restrict__ Wq, const float* __restrict__ Wk,
                 const float* __restrict__ Wv, const float* __restrict__ Wo,
                 __half* __restrict__ xh, __half* __restrict__ ch,
                 __half* __restrict__ wqt, __half* __restrict__ wkt,
                 __half* __restrict__ wvt, __half* __restrict__ wot,
                 uint32_t* __restrict__ mbits)
{
    __shared__ float tsm[32][33];
    const int bid = blockIdx.x;
    const int tid = threadIdx.x;

    if (bid < E_X) {
        tohalf_sub((const float4*)x, (__half2*)xh, bid * 256 + tid);
    } else if (bid < E_C) {
        tohalf_sub((const float4*)ctx, (__half2*)ch, (bid - E_X) * 256 + tid);
    } else if (bid < E_WQ) {
        transT_sub(Wq, wqt, QD_, INNER_, bid - E_C, tid, tsm);
    } else if (bid < E_WK) {
        transT_sub(Wk, wkt, CD_, INNER_, bid - E_WQ, tid, tsm);
    } else if (bid < E_WV) {
        transT_sub(Wv, wvt, CD_, INNER_, bid - E_WK, tid, tsm);
    } else if (bid < E_WO) {
        transT_sub(Wo, wot, INNER_, QD_, bid - E_WV, tid, tsm);
    } else {
        const int w = (bid - E_WO) * 8 + (tid >> 5);
        const int lane = tid & 31;
        const int* row = mask + (size_t)w * NT_;
        uint32_t b0 = __ballot_sync(0xFFFFFFFF, row[lane] != 0);
        uint32_t b1 = __ballot_sync(0xFFFFFFFF, row[32 + lane] != 0);
        uint32_t b2 = __ballot_sync(0xFFFFFFFF, (64 + lane < NT_) ? (row[64 + lane] != 0) : 0);
        if (lane == 0) {
            mbits[(size_t)w * 4 + 0] = b0;
            mbits[(size_t)w * 4 + 1] = b1;
            mbits[(size_t)w * 4 + 2] = b2;
            mbits[(size_t)w * 4 + 3] = 0;
        }
    }
}

// ---------------------------------------------------------------------------
// GEMM core (R12 operating point: 128x128 CTA, 8 warps of 64x32, BK=64,
// 3-stage cp.async, occ 2, KVAL compile-time -> full unroll).
// ---------------------------------------------------------------------------
#define STG_A 0
#define STG_B 16384
#define STG_SIZE 32768
#define NSTAGE 3
#define PIPE_SMEM (NSTAGE * STG_SIZE)   // 98304

#define QY 512
#define KVY 10

template<int KVAL, bool GUARD>
__device__ __forceinline__ void gemm_core(
    const __half* __restrict__ A, const __half* __restrict__ BT,
    float c[4][4][4], uint32_t smem_base,
    int m0, int n0, int M, int tid,
    int warp_m, int warp_n, int lrow, int lchk)
{
    constexpr int NCH = KVAL >> 6;

    auto load_chunk = [&](int s, int k0) {
        const uint32_t sb = smem_base + s * STG_SIZE;
        #pragma unroll
        for (int t = 0; t < 4; t++) {
            const int idx = tid + t * 256;
            const int row = idx >> 3, cc = idx & 7;
            const int ar = GUARD ? min(m0 + row, M - 1) : (m0 + row);
            CP_ASYNC16(sb + STG_A + tile_off64(row, cc),
                       A + (size_t)ar * KVAL + k0 + cc * 8);
        }
        #pragma unroll
        for (int t = 0; t < 4; t++) {
            const int idx = tid + t * 256;
            const int row = idx >> 3, cc = idx & 7;
            CP_ASYNC16(sb + STG_B + tile_off64(row, cc),
                       BT + (size_t)(n0 + row) * KVAL + k0 + cc * 8);
        }
        CP_COMMIT();
    };

    load_chunk(0, 0);
    load_chunk(1, 64);

    #pragma unroll
    for (int ch_ = 0; ch_ < NCH; ch_++) {
        if (ch_ + 1 < NCH) CP_WAIT1(); else CP_WAIT0();
        __syncthreads();

        if (ch_ + 2 < NCH)
            load_chunk((ch_ + 2) % NSTAGE, (ch_ + 2) << 6);

        const uint32_t sb = smem_base + (ch_ % NSTAGE) * STG_SIZE;

        #pragma unroll
        for (int ks = 0; ks < 4; ks++) {
            const int kc = ks * 2;
            uint32_t b[4][2];
            #pragma unroll
            for (int fp = 0; fp < 2; fp++) {
                const int row = warp_n * 32 + fp * 16 + lrow;
                uint32_t r0, r1, r2, r3;
                LDSM_X4(r0, r1, r2, r3, sb + STG_B + tile_off64(row, kc + lchk));
                b[2 * fp + 0][0] = r0; b[2 * fp + 0][1] = r2;
                b[2 * fp + 1][0] = r1; b[2 * fp + 1][1] = r3;
            }
            #pragma unroll
            for (int fm = 0; fm < 4; fm++) {
                const int row = warp_m * 64 + fm * 16 + lrow;
                uint32_t a0, a1, a2, a3;
                LDSM_X4(a0, a1, a2, a3, sb + STG_A + tile_off64(row, kc + lchk));
                #pragma unroll
                for (int fn = 0; fn < 4; fn++)
                    MMA_F16(c[fm][fn][0], c[fm][fn][1], c[fm][fn][2], c[fm][fn][3],
                            a0, a1, a2, a3, b[fn][0], b[fn][1]);
            }
        }
    }
}

// ---------------------------------------------------------------------------
// Merged Q/K/V projection GEMM. KV CTAs (K=768, longest) get the LOWEST
// blockIdx.y so they are scheduled in the first wave, not the tail.
// ---------------------------------------------------------------------------
__global__ __launch_bounds__(256, 2)
void qkv_gemm_pipe(const __half* __restrict__ xh, const __half* __restrict__ wqt,
                   __half* __restrict__ Qh,
                   const __half* __restrict__ ch, const __half* __restrict__ wkt,
                   __half* __restrict__ Kh, const __half* __restrict__ wvt,
                   __half* __restrict__ Vh)
{
    extern __shared__ __align__(1024) char dsm[];
    const uint32_t smem_base = smem_u32(dsm);

    const int by = blockIdx.y;
    const int tid  = threadIdx.x;
    const int wid  = tid >> 5;
    const int lane = tid & 31;
    const int warp_m = wid >> 2;
    const int warp_n = wid & 3;
    const int n0 = blockIdx.x * 128;
    const int N = INNER_;

    float c[4][4][4];
    #pragma unroll
    for (int i = 0; i < 4; i++)
        #pragma unroll
        for (int j = 0; j < 4; j++)
            #pragma unroll
            for (int r = 0; r < 4; r++) c[i][j][r] = 0.f;

    const int lrow = lane & 15;
    const int lchk = lane >> 4;

    __half* C;
    int M, m0;
    bool guard;
    if (by >= 2 * KVY) {
        // Q branch (scheduled after KV)
        M = B_ * NP_; m0 = (by - 2 * KVY) * 128; C = Qh; guard = false;
        gemm_core<QD_, false>(xh, wqt, c, smem_base, m0, n0, M, tid,
                              warp_m, warp_n, lrow, lchk);
    } else {
        // KV branch first (longest CTAs, K=768)
        M = B_ * NT_;
        const __half* BT;
        if (by < KVY) { m0 = by * 128; BT = wkt; C = Kh; }
        else          { m0 = (by - KVY) * 128; BT = wvt; C = Vh; }
        guard = true;
        gemm_core<CD_, true>(ch, BT, c, smem_base, m0, n0, M, tid,
                             warp_m, warp_n, lrow, lchk);
    }

    #pragma unroll
    for (int fm = 0; fm < 4; fm++) {
        const int r0 = m0 + warp_m * 64 + fm * 16 + (lane >> 2);
        #pragma unroll
        for (int fn = 0; fn < 4; fn++) {
            const int col = n0 + warp_n * 32 + fn * 8 + (lane & 3) * 2;
            if (!guard || r0 < M)
                *reinterpret_cast<__half2*>(C + (size_t)r0 * N + col) =
                    __floats2half2_rn(c[fm][fn][0], c[fm][fn][1]);
            if (!guard || r0 + 8 < M)
                *reinterpret_cast<__half2*>(C + (size_t)(r0 + 8) * N + col) =
                    __floats2half2_rn(c[fm][fn][2], c[fm][fn][3]);
        }
    }
}

// ---------------------------------------------------------------------------
// O-projection GEMM (fp32 out + bias, M%128==0, K=INNER_ compile-time).
// ---------------------------------------------------------------------------
__global__ __launch_bounds__(256, 2)
void o_gemm_pipe(const __half* __restrict__ A, const __half* __restrict__ BT,
                 float* __restrict__ C, const float* __restrict__ bias)
{
    extern __shared__ __align__(1024) char dsm[];
    const uint32_t smem_base = smem_u32(dsm);

    const int tid  = threadIdx.x;
    const int wid  = tid >> 5;
    const int lane = tid & 31;
    const int warp_m = wid >> 2;
    const int warp_n = wid & 3;
    const int m0 = blockIdx.y * 128;
    const int n0 = blockIdx.x * 128;
    const int N = QD_;

    float c[4][4][4];
    #pragma unroll
    for (int i = 0; i < 4; i++)
        #pragma unroll
        for (int j = 0; j < 4; j++)
            #pragma unroll
            for (int r = 0; r < 4; r++) c[i][j][r] = 0.f;

    const int lrow = lane & 15;
    const int lchk = lane >> 4;

    gemm_core<INNER_, false>(A, BT, c, smem_base, m0, n0, B_ * NP_, tid,
                             warp_m, warp_n, lrow, lchk);

    #pragma unroll
    for (int fm = 0; fm < 4; fm++) {
        const int r0 = m0 + warp_m * 64 + fm * 16 + (lane >> 2);
        #pragma unroll
        for (int fn = 0; fn < 4; fn++) {
            const int col = n0 + warp_n * 32 + fn * 8 + (lane & 3) * 2;
            const float bx = bias[col], by = bias[col + 1];
            *reinterpret_cast<float2*>(C + (size_t)r0 * N + col) =
                make_float2(c[fm][fn][0] + bx, c[fm][fn][1] + by);
            *reinterpret_cast<float2*>(C + (size_t)(r0 + 8) * N + col) =
                make_float2(c[fm][fn][2] + bx, c[fm][fn][3] + by);
        }
    }
}

// ---------------------------------------------------------------------------
// Tensor-core flash attention; mask via precomputed bitwords.
// __launch_bounds__(256,2): peak live regs ~100 (s[] dies before o[]+p[]
// peak) -> 128-reg cap should avoid spills and give 2 CTAs/SM.
// ---------------------------------------------------------------------------
#define NTP 80
#define QS_PITCH 72
#define VT_PITCH 88

__global__ __launch_bounds__(256, 2)
void fattn_kernel(const __half* __restrict__ Qh, const __half* __restrict__ Kh,
                  const __half* __restrict__ Vh, const uint32_t* __restrict__ mbits,
                  __half* __restrict__ Oh)
{
    __shared__ __half Qs[128 * QS_PITCH];
    __shared__ __half Ks[NTP * QS_PITCH];
    __shared__ __half Vt[DH_ * VT_PITCH];

    const int b = blockIdx.z;
    const int h = blockIdx.y;
    const int q0 = blockIdx.x * 128;
    const int tid = threadIdx.x;
    const int wid = tid >> 5;
    const int lane = tid & 31;

    const uint32_t qs = smem_u32(Qs);
    const uint32_t ks = smem_u32(Ks);
    const uint32_t vt = smem_u32(Vt);

    #pragma unroll
    for (int t = 0; t < 4; t++) {
        const int idx = tid + t * 256;
        const int row = idx >> 3, cc = idx & 7;
        CP_ASYNC16(qs + (row * QS_PITCH + cc * 8) * 2,
                   Qh + ((size_t)(b * NP_ + q0 + row)) * INNER_ + h * DH_ + cc * 8);
    }
    for (int idx = tid; idx < NT_ * 8; idx += 256) {
        const int row = idx >> 3, cc = idx & 7;
        CP_ASYNC16(ks + (row * QS_PITCH + cc * 8) * 2,
                   Kh + ((size_t)(b * NT_ + row)) * INNER_ + h * DH_ + cc * 8);
    }
    CP_COMMIT();

    for (int i = tid; i < 3 * QS_PITCH; i += 256)
        Ks[NT_ * QS_PITCH + i] = __float2half(0.f);
    for (int i = tid; i < DH_ * VT_PITCH / 2; i += 256)
        reinterpret_cast<__half2*>(Vt)[i] = __half2(__float2half(0.f), __float2half(0.f));
    __syncthreads();

    for (int idx = tid; idx < NT_ * DH_; idx += 256) {
        const int t = idx >> 6, d = idx & 63;
        Vt[d * VT_PITCH + t] = Vh[((size_t)(b * NT_ + t)) * INNER_ + h * DH_ + d];
    }
    CP_WAIT0();
    __syncthreads();

    const int lrow = lane & 15;
    const int lchk = lane >> 4;

    float s[10][4];
    #pragma unroll
    for (int f = 0; f < 10; f++)
        #pragma unroll
        for (int r = 0; r < 4; r++) s[f][r] = 0.f;

    #pragma unroll
    for (int kstep = 0; kstep < 4; kstep++) {
        const int kc = kstep * 2;
        uint32_t a0, a1, a2, a3;
        LDSM_X4(a0, a1, a2, a3,
                qs + ((wid * 16 + lrow) * QS_PITCH + (kc + lchk) * 8) * 2);
        #pragma unroll
        for (int g = 0; g < 5; g++) {
            uint32_t r0, r1, r2, r3;
            LDSM_X4(r0, r1, r2, r3,
                    ks + ((g * 16 + lrow) * QS_PITCH + (kc + lchk) * 8) * 2);
            MMA_F16(s[2*g+0][0], s[2*g+0][1], s[2*g+0][2], s[2*g+0][3],
                    a0, a1, a2, a3, r0, r2);
            MMA_F16(s[2*g+1][0], s[2*g+1][1], s[2*g+1][2], s[2*g+1][3],
                    a0, a1, a2, a3, r1, r3);
        }
    }

    const int ra = q0 + wid * 16 + (lane >> 2);
    const int rb = ra + 8;
    const uint32_t* bA = mbits + (size_t)(b * NP_ + ra) * 4;
    const uint32_t* bB = mbits + (size_t)(b * NP_ + rb) * 4;
    const uint32_t a0w = bA[0], a1w = bA[1], a2w = bA[2];
    const uint32_t b0w = bB[0], b1w = bB[1], b2w = bB[2];

    float suma = 0.f, sumb = 0.f;
    #pragma unroll
    for (int f = 0; f < 10; f++) {
        const int t0 = f * 8 + (lane & 3) * 2;
        const uint32_t wa = (f < 4) ? a0w : (f < 8) ? a1w : a2w;
        const uint32_t wb = (f < 4) ? b0w : (f < 8) ? b1w : b2w;
        const int sh = t0 & 31;
        float e0 = ((wa >> sh) & 1)       ? __expf(s[f][0] * 0.125f) : 0.f;
        float e1 = ((wa >> (sh + 1)) & 1) ? __expf(s[f][1] * 0.125f) : 0.f;
        float e2 = ((wb >> sh) & 1)       ? __expf(s[f][2] * 0.125f) : 0.f;
        float e3 = ((wb >> (sh + 1)) & 1) ? __expf(s[f][3] * 0.125f) : 0.f;
        s[f][0] = e0; s[f][1] = e1; s[f][2] = e2; s[f][3] = e3;
        suma += e0 + e1;
        sumb += e2 + e3;
    }
    suma += __shfl_xor_sync(0xFFFFFFFF, suma, 1);
    suma += __shfl_xor_sync(0xFFFFFFFF, suma, 2);
    sumb += __shfl_xor_sync(0xFFFFFFFF, sumb, 1);
    sumb += __shfl_xor_sync(0xFFFFFFFF, sumb, 2);
    const float inva = 1.f / suma;
    const float invb = 1.f / sumb;

    uint32_t p[5][4];
    #pragma unroll
    for (int kstep = 0; kstep < 5; kstep++) {
        const int f0 = 2 * kstep, f1 = 2 * kstep + 1;
        p[kstep][0] = packh2(s[f0][0], s[f0][1]);
        p[kstep][1] = packh2(s[f0][2], s[f0][3]);
        p[kstep][2] = packh2(s[f1][0], s[f1][1]);
        p[kstep][3] = packh2(s[f1][2], s[f1][3]);
    }

    float o[8][4];
    #pragma unroll
    for (int f = 0; f < 8; f++)
        #pragma unroll
        for (int r = 0; r < 4; r++) o[f][r] = 0.f;

    #pragma unroll
    for (int kstep = 0; kstep < 5; kstep++) {
        const int tc = kstep * 2;
        #pragma unroll
        for (int g = 0; g < 4; g++) {
            uint32_t r0, r1, r2, r3;
            LDSM_X4(r0, r1, r2, r3,
                    vt + ((g * 16 + lrow) * VT_PITCH + (tc + lchk) * 8) * 2);
            MMA_F16(o[2*g+0][0], o[2*g+0][1], o[2*g+0][2], o[2*g+0][3],
                    p[kstep][0], p[kstep][1], p[kstep][2], p[kstep][3], r0, r2);
            MMA_F16(o[2*g+1][0], o[2*g+1][1], o[2*g+1][2], o[2*g+1][3],
                    p[kstep][0], p[kstep][1], p[kstep][2], p[kstep][3], r1, r3);
        }
    }

    __half* outA = Oh + ((size_t)(b * NP_ + ra)) * INNER_ + h * DH_;
    __half* outB = Oh + ((size_t)(b * NP_ + rb)) * INNER_ + h * DH_;
    #pragma unroll
    for (int f = 0; f < 8; f++) {
        const int d = f * 8 + (lane & 3) * 2;
        *reinterpret_cast<__half2*>(outA + d) =
            __floats2half2_rn(o[f][0] * inva, o[f][1] * inva);
        *reinterpret_cast<__half2*>(outB + d) =
            __floats2half2_rn(o[f][2] * invb, o[f][3] * invb);
    }
}

// ---------------------------------------------------------------------------
// Launch: 4 kernels total.
// ---------------------------------------------------------------------------
extern "C" void kernel_launch(void* const* d_in, const int* in_sizes, int n_in,
                              void* d_out, int out_size)
{
    const float* x    = (const float*)d_in[0];
    const float* ctx  = (const float*)d_in[1];
    const int*   mask = (const int*)  d_in[2];
    const float* Wq   = (const float*)d_in[3];
    const float* Wk   = (const float*)d_in[4];
    const float* Wv   = (const float*)d_in[5];
    const float* Wo   = (const float*)d_in[6];
    const float* bo   = (const float*)d_in[7];
    float* out = (float*)d_out;

    __half *Qh, *Kh, *Vh, *xh, *ah, *ch, *wqt, *wkt, *wvt, *wot;
    uint32_t* mb;
    cudaGetSymbolAddress((void**)&Qh,  g_Qh);
    cudaGetSymbolAddress((void**)&Kh,  g_Kh);
    cudaGetSymbolAddress((void**)&Vh,  g_Vh);
    cudaGetSymbolAddress((void**)&xh,  g_xh);
    cudaGetSymbolAddress((void**)&ah,  g_ah);
    cudaGetSymbolAddress((void**)&ch,  g_ch);
    cudaGetSymbolAddress((void**)&wqt, g_WqT);
    cudaGetSymbolAddress((void**)&wkt, g_WkT);
    cudaGetSymbolAddress((void**)&wvt, g_WvT);
    cudaGetSymbolAddress((void**)&wot, g_WoT);
    cudaGetSymbolAddress((void**)&mb,  g_mb);

    cudaFuncSetAttribute(qkv_gemm_pipe,
                         cudaFuncAttributeMaxDynamicSharedMemorySize, PIPE_SMEM);
    cudaFuncSetAttribute(o_gemm_pipe,
                         cudaFuncAttributeMaxDynamicSharedMemorySize, PIPE_SMEM);

    const int Mq = B_ * NP_;   // 65536

    // 1) all conversions + mask bits, one launch
    prep_kernel<<<PREP_BLOCKS, 256>>>(x, ctx, mask, Wq, Wk, Wv, Wo,
                                      xh, ch, wqt, wkt, wvt, wot, mb);

    // 2) Q + K + V projections, one launch (KV CTAs scheduled first)
    qkv_gemm_pipe<<<dim3(INNER_ / 128, QY + 2 * KVY, 1), 256, PIPE_SMEM>>>(
        xh, wqt, Qh, ch, wkt, Kh, wvt, Vh);

    // 3) tensor-core flash attention -> fp16
    fattn_kernel<<<dim3(NP_ / 128, H_, B_), 256>>>(Qh, Kh, Vh, mb, ah);

    // 4) out = Att @ Wo + bo
    o_gemm_pipe<<<dim3(QD_ / 128, Mq / 128, 1), 256, PIPE_SMEM>>>(
        ah, wot, out, bo);
}

// round 15
// speedup vs baseline: 1.4159x; 1.1049x over previous
#include <cuda_runtime.h>
#include <cuda_fp16.h>
#include <cstdint>

// Problem constants
#define B_   16
#define NP_  4096
#define NT_  77
#define QD_  512
#define CD_  768
#define H_   8
#define DH_  64
#define INNER_ 512   // H*DH

// ---------------------------------------------------------------------------
// Scratch (device globals)
// ---------------------------------------------------------------------------
__device__ __half    g_Qh [(size_t)B_ * NP_ * INNER_];
__device__ __half    g_Kh [(size_t)B_ * NT_ * INNER_];
__device__ __half    g_Vh [(size_t)B_ * NT_ * INNER_];
__device__ __half    g_xh [(size_t)B_ * NP_ * QD_];
__device__ __half    g_ah [(size_t)B_ * NP_ * INNER_];
__device__ __half    g_ch [(size_t)B_ * NT_ * CD_];
__device__ __half    g_WqT[(size_t)QD_ * INNER_];
__device__ __half    g_WkT[(size_t)CD_ * INNER_];
__device__ __half    g_WvT[(size_t)CD_ * INNER_];
__device__ __half    g_WoT[(size_t)INNER_ * QD_];
__device__ uint32_t  g_mb [(size_t)B_ * NP_ * 4];

// ---------------------------------------------------------------------------
// PTX helpers
// ---------------------------------------------------------------------------
__device__ __forceinline__ uint32_t smem_u32(const void* p) {
    uint32_t a;
    asm("{ .reg .u64 t; cvta.to.shared.u64 t, %1; cvt.u32.u64 %0, t; }" : "=r"(a) : "l"(p));
    return a;
}

#define LDSM_X4(r0, r1, r2, r3, addr) \
    asm volatile("ldmatrix.sync.aligned.m8n8.x4.shared.b16 {%0,%1,%2,%3}, [%4];" \
        : "=r"(r0), "=r"(r1), "=r"(r2), "=r"(r3) : "r"(addr))

#define MMA_F16(c0, c1, c2, c3, a0, a1, a2, a3, b0, b1) \
    asm volatile("mma.sync.aligned.m16n8k16.row.col.f32.f16.f16.f32 " \
        "{%0,%1,%2,%3}, {%4,%5,%6,%7}, {%8,%9}, {%0,%1,%2,%3};" \
        : "+f"(c0), "+f"(c1), "+f"(c2), "+f"(c3) \
        : "r"(a0), "r"(a1), "r"(a2), "r"(a3), "r"(b0), "r"(b1))

#define CP_ASYNC16(dst, src) \
    asm volatile("cp.async.cg.shared.global [%0], [%1], 16;" :: "r"(dst), "l"(src))
#define CP_COMMIT() asm volatile("cp.async.commit_group;" ::: "memory")
#define CP_WAIT1()  asm volatile("cp.async.wait_group 1;" ::: "memory")
#define CP_WAIT0()  asm volatile("cp.async.wait_group 0;" ::: "memory")

// BK=64 smem tile: rows of 64 halves (128B); 16B chunks XOR-swizzled.
__device__ __forceinline__ uint32_t tile_off64(int row, int chunk) {
    return (uint32_t)(row * 128 + ((chunk ^ (row & 7)) << 4));
}

__device__ __forceinline__ uint32_t packh2(float x, float y) {
    __half2 h = __floats2half2_rn(x, y);
    return *reinterpret_cast<uint32_t*>(&h);
}

// ---------------------------------------------------------------------------
// Mega prep kernel (unchanged)
// ---------------------------------------------------------------------------
#define PX_N4   ((B_ * NP_ * QD_) / 4)
#define PC_N4   ((B_ * NT_ * CD_) / 4)
#define PX_BLK  (PX_N4 / 256)
#define PC_BLK  (PC_N4 / 256)
#define WQ_BLK  ((QD_ / 32) * (INNER_ / 32))
#define WK_BLK  ((CD_ / 32) * (INNER_ / 32))
#define WV_BLK  WK_BLK
#define WO_BLK  ((INNER_ / 32) * (QD_ / 32))
#define MB_BLK  ((B_ * NP_) / 8)

#define E_X   PX_BLK
#define E_C   (E_X + PC_BLK)
#define E_WQ  (E_C + WQ_BLK)
#define E_WK  (E_WQ + WK_BLK)
#define E_WV  (E_WK + WV_BLK)
#define E_WO  (E_WV + WO_BLK)
#define E_MB  (E_WO + MB_BLK)
#define PREP_BLOCKS E_MB

__device__ __forceinline__ void tohalf_sub(const float4* in, __half2* out, int i)
{
    float4 v = in[i];
    out[2 * i]     = __floats2half2_rn(v.x, v.y);
    out[2 * i + 1] = __floats2half2_rn(v.z, v.w);
}

__device__ __forceinline__ void transT_sub(const float* in, __half* out,
                                           int K, int N, int t, int tid,
                                           float (*tsm)[33])
{
    const int ktiles = K / 32;
    const int kb = (t % ktiles) * 32;
    const int nb = (t / ktiles) * 32;
    const int tx = tid & 31;
    const int ty = tid >> 5;
    #pragma unroll
    for (int i = 0; i < 32; i += 8)
        tsm[ty + i][tx] = in[(size_t)(kb + ty + i) * N + nb + tx];
    __syncthreads();
    #pragma unroll
    for (int i = 0; i < 32; i += 8)
        out[(size_t)(nb + ty + i) * K + kb + tx] = __float2half_rn(tsm[tx][ty + i]);
}

__global__ __launch_bounds__(256)
void prep_kernel(const float* __restrict__ x, const float* __restrict__ ctx,
                 const int* __restrict__ mask,
                 const float* __restrict__ Wq, const float* __restrict__ Wk,
                 const float* __restrict__ Wv, const float* __restrict__ Wo,
                 __half* __restrict__ xh, __half* __restrict__ ch,
                 __half* __restrict__ wqt, __half* __restrict__ wkt,
                 __half* __restrict__ wvt, __half* __restrict__ wot,
                 uint32_t* __restrict__ mbits)
{
    __shared__ float tsm[32][33];
    const int bid = blockIdx.x;
    const int tid = threadIdx.x;

    if (bid < E_X) {
        tohalf_sub((const float4*)x, (__half2*)xh, bid * 256 + tid);
    } else if (bid < E_C) {
        tohalf_sub((const float4*)ctx, (__half2*)ch, (bid - E_X) * 256 + tid);
    } else if (bid < E_WQ) {
        transT_sub(Wq, wqt, QD_, INNER_, bid - E_C, tid, tsm);
    } else if (bid < E_WK) {
        transT_sub(Wk, wkt, CD_, INNER_, bid - E_WQ, tid, tsm);
    } else if (bid < E_WV) {
        transT_sub(Wv, wvt, CD_, INNER_, bid - E_WK, tid, tsm);
    } else if (bid < E_WO) {
        transT_sub(Wo, wot, INNER_, QD_, bid - E_WV, tid, tsm);
    } else {
        const int w = (bid - E_WO) * 8 + (tid >> 5);
        const int lane = tid & 31;
        const int* row = mask + (size_t)w * NT_;
        uint32_t b0 = __ballot_sync(0xFFFFFFFF, row[lane] != 0);
        uint32_t b1 = __ballot_sync(0xFFFFFFFF, row[32 + lane] != 0);
        uint32_t b2 = __ballot_sync(0xFFFFFFFF, (64 + lane < NT_) ? (row[64 + lane] != 0) : 0);
        if (lane == 0) {
            mbits[(size_t)w * 4 + 0] = b0;
            mbits[(size_t)w * 4 + 1] = b1;
            mbits[(size_t)w * 4 + 2] = b2;
            mbits[(size_t)w * 4 + 3] = 0;
        }
    }
}

// ---------------------------------------------------------------------------
// GEMM core (R12 operating point: 128x128 CTA, 8 warps of 64x32, BK=64,
// 3-stage cp.async, occ 2, KVAL compile-time -> full unroll).
// ---------------------------------------------------------------------------
#define STG_A 0
#define STG_B 16384
#define STG_SIZE 32768
#define NSTAGE 3
#define PIPE_SMEM (NSTAGE * STG_SIZE)   // 98304

#define QY 512
#define KVY 10

template<int KVAL, bool GUARD>
__device__ __forceinline__ void gemm_core(
    const __half* __restrict__ A, const __half* __restrict__ BT,
    float c[4][4][4], uint32_t smem_base,
    int m0, int n0, int M, int tid,
    int warp_m, int warp_n, int lrow, int lchk)
{
    constexpr int NCH = KVAL >> 6;

    auto load_chunk = [&](int s, int k0) {
        const uint32_t sb = smem_base + s * STG_SIZE;
        #pragma unroll
        for (int t = 0; t < 4; t++) {
            const int idx = tid + t * 256;
            const int row = idx >> 3, cc = idx & 7;
            const int ar = GUARD ? min(m0 + row, M - 1) : (m0 + row);
            CP_ASYNC16(sb + STG_A + tile_off64(row, cc),
                       A + (size_t)ar * KVAL + k0 + cc * 8);
        }
        #pragma unroll
        for (int t = 0; t < 4; t++) {
            const int idx = tid + t * 256;
            const int row = idx >> 3, cc = idx & 7;
            CP_ASYNC16(sb + STG_B + tile_off64(row, cc),
                       BT + (size_t)(n0 + row) * KVAL + k0 + cc * 8);
        }
        CP_COMMIT();
    };

    load_chunk(0, 0);
    load_chunk(1, 64);

    #pragma unroll
    for (int ch_ = 0; ch_ < NCH; ch_++) {
        if (ch_ + 1 < NCH) CP_WAIT1(); else CP_WAIT0();
        __syncthreads();

        if (ch_ + 2 < NCH)
            load_chunk((ch_ + 2) % NSTAGE, (ch_ + 2) << 6);

        const uint32_t sb = smem_base + (ch_ % NSTAGE) * STG_SIZE;

        #pragma unroll
        for (int ks = 0; ks < 4; ks++) {
            const int kc = ks * 2;
            uint32_t b[4][2];
            #pragma unroll
            for (int fp = 0; fp < 2; fp++) {
                const int row = warp_n * 32 + fp * 16 + lrow;
                uint32_t r0, r1, r2, r3;
                LDSM_X4(r0, r1, r2, r3, sb + STG_B + tile_off64(row, kc + lchk));
                b[2 * fp + 0][0] = r0; b[2 * fp + 0][1] = r2;
                b[2 * fp + 1][0] = r1; b[2 * fp + 1][1] = r3;
            }
            #pragma unroll
            for (int fm = 0; fm < 4; fm++) {
                const int row = warp_m * 64 + fm * 16 + lrow;
                uint32_t a0, a1, a2, a3;
                LDSM_X4(a0, a1, a2, a3, sb + STG_A + tile_off64(row, kc + lchk));
                #pragma unroll
                for (int fn = 0; fn < 4; fn++)
                    MMA_F16(c[fm][fn][0], c[fm][fn][1], c[fm][fn][2], c[fm][fn][3],
                            a0, a1, a2, a3, b[fn][0], b[fn][1]);
            }
        }
    }
}

// ---------------------------------------------------------------------------
// Merged Q/K/V projection GEMM. KV CTAs (K=768, longest) get the LOWEST
// blockIdx.y so they are scheduled in the first wave, not the tail.
// ---------------------------------------------------------------------------
__global__ __launch_bounds__(256, 2)
void qkv_gemm_pipe(const __half* __restrict__ xh, const __half* __restrict__ wqt,
                   __half* __restrict__ Qh,
                   const __half* __restrict__ ch, const __half* __restrict__ wkt,
                   __half* __restrict__ Kh, const __half* __restrict__ wvt,
                   __half* __restrict__ Vh)
{
    extern __shared__ __align__(1024) char dsm[];
    const uint32_t smem_base = smem_u32(dsm);

    const int by = blockIdx.y;
    const int tid  = threadIdx.x;
    const int wid  = tid >> 5;
    const int lane = tid & 31;
    const int warp_m = wid >> 2;
    const int warp_n = wid & 3;
    const int n0 = blockIdx.x * 128;
    const int N = INNER_;

    float c[4][4][4];
    #pragma unroll
    for (int i = 0; i < 4; i++)
        #pragma unroll
        for (int j = 0; j < 4; j++)
            #pragma unroll
            for (int r = 0; r < 4; r++) c[i][j][r] = 0.f;

    const int lrow = lane & 15;
    const int lchk = lane >> 4;

    __half* C;
    int M, m0;
    bool guard;
    if (by >= 2 * KVY) {
        // Q branch (scheduled after KV)
        M = B_ * NP_; m0 = (by - 2 * KVY) * 128; C = Qh; guard = false;
        gemm_core<QD_, false>(xh, wqt, c, smem_base, m0, n0, M, tid,
                              warp_m, warp_n, lrow, lchk);
    } else {
        // KV branch first (longest CTAs, K=768)
        M = B_ * NT_;
        const __half* BT;
        if (by < KVY) { m0 = by * 128; BT = wkt; C = Kh; }
        else          { m0 = (by - KVY) * 128; BT = wvt; C = Vh; }
        guard = true;
        gemm_core<CD_, true>(ch, BT, c, smem_base, m0, n0, M, tid,
                             warp_m, warp_n, lrow, lchk);
    }

    #pragma unroll
    for (int fm = 0; fm < 4; fm++) {
        const int r0 = m0 + warp_m * 64 + fm * 16 + (lane >> 2);
        #pragma unroll
        for (int fn = 0; fn < 4; fn++) {
            const int col = n0 + warp_n * 32 + fn * 8 + (lane & 3) * 2;
            if (!guard || r0 < M)
                *reinterpret_cast<__half2*>(C + (size_t)r0 * N + col) =
                    __floats2half2_rn(c[fm][fn][0], c[fm][fn][1]);
            if (!guard || r0 + 8 < M)
                *reinterpret_cast<__half2*>(C + (size_t)(r0 + 8) * N + col) =
                    __floats2half2_rn(c[fm][fn][2], c[fm][fn][3]);
        }
    }
}

// ---------------------------------------------------------------------------
// O-projection GEMM (fp32 out + bias, M%128==0, K=INNER_ compile-time).
// Bias loads hoisted out of the fm loop (fn-dependent only).
// ---------------------------------------------------------------------------
__global__ __launch_bounds__(256, 2)
void o_gemm_pipe(const __half* __restrict__ A, const __half* __restrict__ BT,
                 float* __restrict__ C, const float* __restrict__ bias)
{
    extern __shared__ __align__(1024) char dsm[];
    const uint32_t smem_base = smem_u32(dsm);

    const int tid  = threadIdx.x;
    const int wid  = tid >> 5;
    const int lane = tid & 31;
    const int warp_m = wid >> 2;
    const int warp_n = wid & 3;
    const int m0 = blockIdx.y * 128;
    const int n0 = blockIdx.x * 128;
    const int N = QD_;

    float c[4][4][4];
    #pragma unroll
    for (int i = 0; i < 4; i++)
        #pragma unroll
        for (int j = 0; j < 4; j++)
            #pragma unroll
            for (int r = 0; r < 4; r++) c[i][j][r] = 0.f;

    const int lrow = lane & 15;
    const int lchk = lane >> 4;

    gemm_core<INNER_, false>(A, BT, c, smem_base, m0, n0, B_ * NP_, tid,
                             warp_m, warp_n, lrow, lchk);

    // hoist bias (depends only on fn)
    float bx[4], by_[4];
    #pragma unroll
    for (int fn = 0; fn < 4; fn++) {
        const int col = n0 + warp_n * 32 + fn * 8 + (lane & 3) * 2;
        bx[fn] = bias[col];
        by_[fn] = bias[col + 1];
    }

    #pragma unroll
    for (int fm = 0; fm < 4; fm++) {
        const int r0 = m0 + warp_m * 64 + fm * 16 + (lane >> 2);
        #pragma unroll
        for (int fn = 0; fn < 4; fn++) {
            const int col = n0 + warp_n * 32 + fn * 8 + (lane & 3) * 2;
            *reinterpret_cast<float2*>(C + (size_t)r0 * N + col) =
                make_float2(c[fm][fn][0] + bx[fn], c[fm][fn][1] + by_[fn]);
            *reinterpret_cast<float2*>(C + (size_t)(r0 + 8) * N + col) =
                make_float2(c[fm][fn][2] + bx[fn], c[fm][fn][3] + by_[fn]);
        }
    }
}

// ---------------------------------------------------------------------------
// Tensor-core flash attention (exact R12 version; NO launch-bounds cap —
// forcing 2 CTAs/SM caused register spills and a 50us regression in R14).
// ---------------------------------------------------------------------------
#define NTP 80
#define QS_PITCH 72
#define VT_PITCH 88

__global__ __launch_bounds__(256)
void fattn_kernel(const __half* __restrict__ Qh, const __half* __restrict__ Kh,
                  const __half* __restrict__ Vh, const uint32_t* __restrict__ mbits,
                  __half* __restrict__ Oh)
{
    __shared__ __half Qs[128 * QS_PITCH];
    __shared__ __half Ks[NTP * QS_PITCH];
    __shared__ __half Vt[DH_ * VT_PITCH];

    const int b = blockIdx.z;
    const int h = blockIdx.y;
    const int q0 = blockIdx.x * 128;
    const int tid = threadIdx.x;
    const int wid = tid >> 5;
    const int lane = tid & 31;

    const uint32_t qs = smem_u32(Qs);
    const uint32_t ks = smem_u32(Ks);
    const uint32_t vt = smem_u32(Vt);

    #pragma unroll
    for (int t = 0; t < 4; t++) {
        const int idx = tid + t * 256;
        const int row = idx >> 3, cc = idx & 7;
        CP_ASYNC16(qs + (row * QS_PITCH + cc * 8) * 2,
                   Qh + ((size_t)(b * NP_ + q0 + row)) * INNER_ + h * DH_ + cc * 8);
    }
    for (int idx = tid; idx < NT_ * 8; idx += 256) {
        const int row = idx >> 3, cc = idx & 7;
        CP_ASYNC16(ks + (row * QS_PITCH + cc * 8) * 2,
                   Kh + ((size_t)(b * NT_ + row)) * INNER_ + h * DH_ + cc * 8);
    }
    CP_COMMIT();

    for (int i = tid; i < 3 * QS_PITCH; i += 256)
        Ks[NT_ * QS_PITCH + i] = __float2half(0.f);
    for (int i = tid; i < DH_ * VT_PITCH / 2; i += 256)
        reinterpret_cast<__half2*>(Vt)[i] = __half2(__float2half(0.f), __float2half(0.f));
    __syncthreads();

    for (int idx = tid; idx < NT_ * DH_; idx += 256) {
        const int t = idx >> 6, d = idx & 63;
        Vt[d * VT_PITCH + t] = Vh[((size_t)(b * NT_ + t)) * INNER_ + h * DH_ + d];
    }
    CP_WAIT0();
    __syncthreads();

    const int lrow = lane & 15;
    const int lchk = lane >> 4;

    float s[10][4];
    #pragma unroll
    for (int f = 0; f < 10; f++)
        #pragma unroll
        for (int r = 0; r < 4; r++) s[f][r] = 0.f;

    #pragma unroll
    for (int kstep = 0; kstep < 4; kstep++) {
        const int kc = kstep * 2;
        uint32_t a0, a1, a2, a3;
        LDSM_X4(a0, a1, a2, a3,
                qs + ((wid * 16 + lrow) * QS_PITCH + (kc + lchk) * 8) * 2);
        #pragma unroll
        for (int g = 0; g < 5; g++) {
            uint32_t r0, r1, r2, r3;
            LDSM_X4(r0, r1, r2, r3,
                    ks + ((g * 16 + lrow) * QS_PITCH + (kc + lchk) * 8) * 2);
            MMA_F16(s[2*g+0][0], s[2*g+0][1], s[2*g+0][2], s[2*g+0][3],
                    a0, a1, a2, a3, r0, r2);
            MMA_F16(s[2*g+1][0], s[2*g+1][1], s[2*g+1][2], s[2*g+1][3],
                    a0, a1, a2, a3, r1, r3);
        }
    }

    const int ra = q0 + wid * 16 + (lane >> 2);
    const int rb = ra + 8;
    const uint32_t* bA = mbits + (size_t)(b * NP_ + ra) * 4;
    const uint32_t* bB = mbits + (size_t)(b * NP_ + rb) * 4;
    const uint32_t a0w = bA[0], a1w = bA[1], a2w = bA[2];
    const uint32_t b0w = bB[0], b1w = bB[1], b2w = bB[2];

    float suma = 0.f, sumb = 0.f;
    #pragma unroll
    for (int f = 0; f < 10; f++) {
        const int t0 = f * 8 + (lane & 3) * 2;
        const uint32_t wa = (f < 4) ? a0w : (f < 8) ? a1w : a2w;
        const uint32_t wb = (f < 4) ? b0w : (f < 8) ? b1w : b2w;
        const int sh = t0 & 31;
        float e0 = ((wa >> sh) & 1)       ? __expf(s[f][0] * 0.125f) : 0.f;
        float e1 = ((wa >> (sh + 1)) & 1) ? __expf(s[f][1] * 0.125f) : 0.f;
        float e2 = ((wb >> sh) & 1)       ? __expf(s[f][2] * 0.125f) : 0.f;
        float e3 = ((wb >> (sh + 1)) & 1) ? __expf(s[f][3] * 0.125f) : 0.f;
        s[f][0] = e0; s[f][1] = e1; s[f][2] = e2; s[f][3] = e3;
        suma += e0 + e1;
        sumb += e2 + e3;
    }
    suma += __shfl_xor_sync(0xFFFFFFFF, suma, 1);
    suma += __shfl_xor_sync(0xFFFFFFFF, suma, 2);
    sumb += __shfl_xor_sync(0xFFFFFFFF, sumb, 1);
    sumb += __shfl_xor_sync(0xFFFFFFFF, sumb, 2);
    const float inva = 1.f / suma;
    const float invb = 1.f / sumb;

    uint32_t p[5][4];
    #pragma unroll
    for (int kstep = 0; kstep < 5; kstep++) {
        const int f0 = 2 * kstep, f1 = 2 * kstep + 1;
        p[kstep][0] = packh2(s[f0][0], s[f0][1]);
        p[kstep][1] = packh2(s[f0][2], s[f0][3]);
        p[kstep][2] = packh2(s[f1][0], s[f1][1]);
        p[kstep][3] = packh2(s[f1][2], s[f1][3]);
    }

    float o[8][4];
    #pragma unroll
    for (int f = 0; f < 8; f++)
        #pragma unroll
        for (int r = 0; r < 4; r++) o[f][r] = 0.f;

    #pragma unroll
    for (int kstep = 0; kstep < 5; kstep++) {
        const int tc = kstep * 2;
        #pragma unroll
        for (int g = 0; g < 4; g++) {
            uint32_t r0, r1, r2, r3;
            LDSM_X4(r0, r1, r2, r3,
                    vt + ((g * 16 + lrow) * VT_PITCH + (tc + lchk) * 8) * 2);
            MMA_F16(o[2*g+0][0], o[2*g+0][1], o[2*g+0][2], o[2*g+0][3],
                    p[kstep][0], p[kstep][1], p[kstep][2], p[kstep][3], r0, r2);
            MMA_F16(o[2*g+1][0], o[2*g+1][1], o[2*g+1][2], o[2*g+1][3],
                    p[kstep][0], p[kstep][1], p[kstep][2], p[kstep][3], r1, r3);
        }
    }

    __half* outA = Oh + ((size_t)(b * NP_ + ra)) * INNER_ + h * DH_;
    __half* outB = Oh + ((size_t)(b * NP_ + rb)) * INNER_ + h * DH_;
    #pragma unroll
    for (int f = 0; f < 8; f++) {
        const int d = f * 8 + (lane & 3) * 2;
        *reinterpret_cast<__half2*>(outA + d) =
            __floats2half2_rn(o[f][0] * inva, o[f][1] * inva);
        *reinterpret_cast<__half2*>(outB + d) =
            __floats2half2_rn(o[f][2] * invb, o[f][3] * invb);
    }
}

// ---------------------------------------------------------------------------
// Launch: 4 kernels total.
// ---------------------------------------------------------------------------
extern "C" void kernel_launch(void* const* d_in, const int* in_sizes, int n_in,
                              void* d_out, int out_size)
{
    const float* x    = (const float*)d_in[0];
    const float* ctx  = (const float*)d_in[1];
    const int*   mask = (const int*)  d_in[2];
    const float* Wq   = (const float*)d_in[3];
    const float* Wk   = (const float*)d_in[4];
    const float* Wv   = (const float*)d_in[5];
    const float* Wo   = (const float*)d_in[6];
    const float* bo   = (const float*)d_in[7];
    float* out = (float*)d_out;

    __half *Qh, *Kh, *Vh, *xh, *ah, *ch, *wqt, *wkt, *wvt, *wot;
    uint32_t* mb;
    cudaGetSymbolAddress((void**)&Qh,  g_Qh);
    cudaGetSymbolAddress((void**)&Kh,  g_Kh);
    cudaGetSymbolAddress((void**)&Vh,  g_Vh);
    cudaGetSymbolAddress((void**)&xh,  g_xh);
    cudaGetSymbolAddress((void**)&ah,  g_ah);
    cudaGetSymbolAddress((void**)&ch,  g_ch);
    cudaGetSymbolAddress((void**)&wqt, g_WqT);
    cudaGetSymbolAddress((void**)&wkt, g_WkT);
    cudaGetSymbolAddress((void**)&wvt, g_WvT);
    cudaGetSymbolAddress((void**)&wot, g_WoT);
    cudaGetSymbolAddress((void**)&mb,  g_mb);

    cudaFuncSetAttribute(qkv_gemm_pipe,
                         cudaFuncAttributeMaxDynamicSharedMemorySize, PIPE_SMEM);
    cudaFuncSetAttribute(o_gemm_pipe,
                         cudaFuncAttributeMaxDynamicSharedMemorySize, PIPE_SMEM);

    const int Mq = B_ * NP_;   // 65536

    // 1) all conversions + mask bits, one launch
    prep_kernel<<<PREP_BLOCKS, 256>>>(x, ctx, mask, Wq, Wk, Wv, Wo,
                                      xh, ch, wqt, wkt, wvt, wot, mb);

    // 2) Q + K + V projections, one launch (KV CTAs scheduled first)
    qkv_gemm_pipe<<<dim3(INNER_ / 128, QY + 2 * KVY, 1), 256, PIPE_SMEM>>>(
        xh, wqt, Qh, ch, wkt, Kh, wvt, Vh);

    // 3) tensor-core flash attention -> fp16
    fattn_kernel<<<dim3(NP_ / 128, H_, B_), 256>>>(Qh, Kh, Vh, mb, ah);

    // 4) out = Att @ Wo + bo
    o_gemm_pipe<<<dim3(QD_ / 128, Mq / 128, 1), 256, PIPE_SMEM>>>(
        ah, wot, out, bo);
}

// round 16
// speedup vs baseline: 1.5172x; 1.0716x over previous
#include <cuda_runtime.h>
#include <cuda_fp16.h>
#include <cstdint>

// Problem constants
#define B_   16
#define NP_  4096
#define NT_  77
#define QD_  512
#define CD_  768
#define H_   8
#define DH_  64
#define INNER_ 512   // H*DH

// ---------------------------------------------------------------------------
// Scratch (device globals)
// ---------------------------------------------------------------------------
__device__ __half    g_Qh [(size_t)B_ * NP_ * INNER_];
__device__ __half    g_Kh [(size_t)B_ * NT_ * INNER_];
__device__ __half    g_Vh [(size_t)B_ * NT_ * INNER_];
__device__ __half    g_xh [(size_t)B_ * NP_ * QD_];
__device__ __half    g_ah [(size_t)B_ * NP_ * INNER_];
__device__ __half    g_ch [(size_t)B_ * NT_ * CD_];
__device__ __half    g_WqT[(size_t)QD_ * INNER_];
__device__ __half    g_WkT[(size_t)CD_ * INNER_];
__device__ __half    g_WvT[(size_t)CD_ * INNER_];
__device__ __half    g_WoT[(size_t)INNER_ * QD_];
__device__ uint32_t  g_mb [(size_t)B_ * NP_ * 4];

// ---------------------------------------------------------------------------
// PTX helpers
// ---------------------------------------------------------------------------
__device__ __forceinline__ uint32_t smem_u32(const void* p) {
    uint32_t a;
    asm("{ .reg .u64 t; cvta.to.shared.u64 t, %1; cvt.u32.u64 %0, t; }" : "=r"(a) : "l"(p));
    return a;
}

#define LDSM_X4(r0, r1, r2, r3, addr) \
    asm volatile("ldmatrix.sync.aligned.m8n8.x4.shared.b16 {%0,%1,%2,%3}, [%4];" \
        : "=r"(r0), "=r"(r1), "=r"(r2), "=r"(r3) : "r"(addr))

#define MMA_F16(c0, c1, c2, c3, a0, a1, a2, a3, b0, b1) \
    asm volatile("mma.sync.aligned.m16n8k16.row.col.f32.f16.f16.f32 " \
        "{%0,%1,%2,%3}, {%4,%5,%6,%7}, {%8,%9}, {%0,%1,%2,%3};" \
        : "+f"(c0), "+f"(c1), "+f"(c2), "+f"(c3) \
        : "r"(a0), "r"(a1), "r"(a2), "r"(a3), "r"(b0), "r"(b1))

#define CP_ASYNC16(dst, src) \
    asm volatile("cp.async.cg.shared.global [%0], [%1], 16;" :: "r"(dst), "l"(src))
#define CP_COMMIT() asm volatile("cp.async.commit_group;" ::: "memory")
#define CP_WAIT1()  asm volatile("cp.async.wait_group 1;" ::: "memory")
#define CP_WAIT0()  asm volatile("cp.async.wait_group 0;" ::: "memory")

// BK=64 smem tile: rows of 64 halves (128B); 16B chunks XOR-swizzled.
__device__ __forceinline__ uint32_t tile_off64(int row, int chunk) {
    return (uint32_t)(row * 128 + ((chunk ^ (row & 7)) << 4));
}

__device__ __forceinline__ uint32_t packh2(float x, float y) {
    __half2 h = __floats2half2_rn(x, y);
    return *reinterpret_cast<uint32_t*>(&h);
}

// ---------------------------------------------------------------------------
// Mega prep kernel (unchanged)
// ---------------------------------------------------------------------------
#define PX_N4   ((B_ * NP_ * QD_) / 4)
#define PC_N4   ((B_ * NT_ * CD_) / 4)
#define PX_BLK  (PX_N4 / 256)
#define PC_BLK  (PC_N4 / 256)
#define WQ_BLK  ((QD_ / 32) * (INNER_ / 32))
#define WK_BLK  ((CD_ / 32) * (INNER_ / 32))
#define WV_BLK  WK_BLK
#define WO_BLK  ((INNER_ / 32) * (QD_ / 32))
#define MB_BLK  ((B_ * NP_) / 8)

#define E_X   PX_BLK
#define E_C   (E_X + PC_BLK)
#define E_WQ  (E_C + WQ_BLK)
#define E_WK  (E_WQ + WK_BLK)
#define E_WV  (E_WK + WV_BLK)
#define E_WO  (E_WV + WO_BLK)
#define E_MB  (E_WO + MB_BLK)
#define PREP_BLOCKS E_MB

__device__ __forceinline__ void tohalf_sub(const float4* in, __half2* out, int i)
{
    float4 v = in[i];
    out[2 * i]     = __floats2half2_rn(v.x, v.y);
    out[2 * i + 1] = __floats2half2_rn(v.z, v.w);
}

__device__ __forceinline__ void transT_sub(const float* in, __half* out,
                                           int K, int N, int t, int tid,
                                           float (*tsm)[33])
{
    const int ktiles = K / 32;
    const int kb = (t % ktiles) * 32;
    const int nb = (t / ktiles) * 32;
    const int tx = tid & 31;
    const int ty = tid >> 5;
    #pragma unroll
    for (int i = 0; i < 32; i += 8)
        tsm[ty + i][tx] = in[(size_t)(kb + ty + i) * N + nb + tx];
    __syncthreads();
    #pragma unroll
    for (int i = 0; i < 32; i += 8)
        out[(size_t)(nb + ty + i) * K + kb + tx] = __float2half_rn(tsm[tx][ty + i]);
}

__global__ __launch_bounds__(256)
void prep_kernel(const float* __restrict__ x, const float* __restrict__ ctx,
                 const int* __restrict__ mask,
                 const float* __restrict__ Wq, const float* __restrict__ Wk,
                 const float* __restrict__ Wv, const float* __restrict__ Wo,
                 __half* __restrict__ xh, __half* __restrict__ ch,
                 __half* __restrict__ wqt, __half* __restrict__ wkt,
                 __half* __restrict__ wvt, __half* __restrict__ wot,
                 uint32_t* __restrict__ mbits)
{
    __shared__ float tsm[32][33];
    const int bid = blockIdx.x;
    const int tid = threadIdx.x;

    if (bid < E_X) {
        tohalf_sub((const float4*)x, (__half2*)xh, bid * 256 + tid);
    } else if (bid < E_C) {
        tohalf_sub((const float4*)ctx, (__half2*)ch, (bid - E_X) * 256 + tid);
    } else if (bid < E_WQ) {
        transT_sub(Wq, wqt, QD_, INNER_, bid - E_C, tid, tsm);
    } else if (bid < E_WK) {
        transT_sub(Wk, wkt, CD_, INNER_, bid - E_WQ, tid, tsm);
    } else if (bid < E_WV) {
        transT_sub(Wv, wvt, CD_, INNER_, bid - E_WK, tid, tsm);
    } else if (bid < E_WO) {
        transT_sub(Wo, wot, INNER_, QD_, bid - E_WV, tid, tsm);
    } else {
        const int w = (bid - E_WO) * 8 + (tid >> 5);
        const int lane = tid & 31;
        const int* row = mask + (size_t)w * NT_;
        uint32_t b0 = __ballot_sync(0xFFFFFFFF, row[lane] != 0);
        uint32_t b1 = __ballot_sync(0xFFFFFFFF, row[32 + lane] != 0);
        uint32_t b2 = __ballot_sync(0xFFFFFFFF, (64 + lane < NT_) ? (row[64 + lane] != 0) : 0);
        if (lane == 0) {
            mbits[(size_t)w * 4 + 0] = b0;
            mbits[(size_t)w * 4 + 1] = b1;
            mbits[(size_t)w * 4 + 2] = b2;
            mbits[(size_t)w * 4 + 3] = 0;
        }
    }
}

// ---------------------------------------------------------------------------
// GEMM core (R12 operating point: 128x128 CTA, 8 warps of 64x32, BK=64,
// 3-stage cp.async, occ 2, KVAL compile-time -> full unroll).
// ---------------------------------------------------------------------------
#define STG_A 0
#define STG_B 16384
#define STG_SIZE 32768
#define NSTAGE 3
#define PIPE_SMEM (NSTAGE * STG_SIZE)   // 98304

#define QY 512
#define KVY 10

template<int KVAL, bool GUARD>
__device__ __forceinline__ void gemm_core(
    const __half* __restrict__ A, const __half* __restrict__ BT,
    float c[4][4][4], uint32_t smem_base,
    int m0, int n0, int M, int tid,
    int warp_m, int warp_n, int lrow, int lchk)
{
    constexpr int NCH = KVAL >> 6;

    auto load_chunk = [&](int s, int k0) {
        const uint32_t sb = smem_base + s * STG_SIZE;
        #pragma unroll
        for (int t = 0; t < 4; t++) {
            const int idx = tid + t * 256;
            const int row = idx >> 3, cc = idx & 7;
            const int ar = GUARD ? min(m0 + row, M - 1) : (m0 + row);
            CP_ASYNC16(sb + STG_A + tile_off64(row, cc),
                       A + (size_t)ar * KVAL + k0 + cc * 8);
        }
        #pragma unroll
        for (int t = 0; t < 4; t++) {
            const int idx = tid + t * 256;
            const int row = idx >> 3, cc = idx & 7;
            CP_ASYNC16(sb + STG_B + tile_off64(row, cc),
                       BT + (size_t)(n0 + row) * KVAL + k0 + cc * 8);
        }
        CP_COMMIT();
    };

    load_chunk(0, 0);
    load_chunk(1, 64);

    #pragma unroll
    for (int ch_ = 0; ch_ < NCH; ch_++) {
        if (ch_ + 1 < NCH) CP_WAIT1(); else CP_WAIT0();
        __syncthreads();

        if (ch_ + 2 < NCH)
            load_chunk((ch_ + 2) % NSTAGE, (ch_ + 2) << 6);

        const uint32_t sb = smem_base + (ch_ % NSTAGE) * STG_SIZE;

        #pragma unroll
        for (int ks = 0; ks < 4; ks++) {
            const int kc = ks * 2;
            uint32_t b[4][2];
            #pragma unroll
            for (int fp = 0; fp < 2; fp++) {
                const int row = warp_n * 32 + fp * 16 + lrow;
                uint32_t r0, r1, r2, r3;
                LDSM_X4(r0, r1, r2, r3, sb + STG_B + tile_off64(row, kc + lchk));
                b[2 * fp + 0][0] = r0; b[2 * fp + 0][1] = r2;
                b[2 * fp + 1][0] = r1; b[2 * fp + 1][1] = r3;
            }
            #pragma unroll
            for (int fm = 0; fm < 4; fm++) {
                const int row = warp_m * 64 + fm * 16 + lrow;
                uint32_t a0, a1, a2, a3;
                LDSM_X4(a0, a1, a2, a3, sb + STG_A + tile_off64(row, kc + lchk));
                #pragma unroll
                for (int fn = 0; fn < 4; fn++)
                    MMA_F16(c[fm][fn][0], c[fm][fn][1], c[fm][fn][2], c[fm][fn][3],
                            a0, a1, a2, a3, b[fn][0], b[fn][1]);
            }
        }
    }
}

// ---------------------------------------------------------------------------
// Merged Q/K/V projection GEMM (R12 ordering: Q branch FIRST — hot path
// first in the binary; KV-first cost ~13us of I-fetch in R15).
// ---------------------------------------------------------------------------
__global__ __launch_bounds__(256, 2)
void qkv_gemm_pipe(const __half* __restrict__ xh, const __half* __restrict__ wqt,
                   __half* __restrict__ Qh,
                   const __half* __restrict__ ch, const __half* __restrict__ wkt,
                   __half* __restrict__ Kh, const __half* __restrict__ wvt,
                   __half* __restrict__ Vh)
{
    extern __shared__ __align__(1024) char dsm[];
    const uint32_t smem_base = smem_u32(dsm);

    const int by = blockIdx.y;
    const int tid  = threadIdx.x;
    const int wid  = tid >> 5;
    const int lane = tid & 31;
    const int warp_m = wid >> 2;
    const int warp_n = wid & 3;
    const int n0 = blockIdx.x * 128;
    const int N = INNER_;

    float c[4][4][4];
    #pragma unroll
    for (int i = 0; i < 4; i++)
        #pragma unroll
        for (int j = 0; j < 4; j++)
            #pragma unroll
            for (int r = 0; r < 4; r++) c[i][j][r] = 0.f;

    const int lrow = lane & 15;
    const int lchk = lane >> 4;

    __half* C;
    int M, m0;
    bool guard;
    if (by < QY) {
        M = B_ * NP_; m0 = by * 128; C = Qh; guard = false;
        gemm_core<QD_, false>(xh, wqt, c, smem_base, m0, n0, M, tid,
                              warp_m, warp_n, lrow, lchk);
    } else {
        M = B_ * NT_;
        const __half* BT;
        if (by < QY + KVY) { m0 = (by - QY) * 128; BT = wkt; C = Kh; }
        else               { m0 = (by - QY - KVY) * 128; BT = wvt; C = Vh; }
        guard = true;
        gemm_core<CD_, true>(ch, BT, c, smem_base, m0, n0, M, tid,
                             warp_m, warp_n, lrow, lchk);
    }

    #pragma unroll
    for (int fm = 0; fm < 4; fm++) {
        const int r0 = m0 + warp_m * 64 + fm * 16 + (lane >> 2);
        #pragma unroll
        for (int fn = 0; fn < 4; fn++) {
            const int col = n0 + warp_n * 32 + fn * 8 + (lane & 3) * 2;
            if (!guard || r0 < M)
                *reinterpret_cast<__half2*>(C + (size_t)r0 * N + col) =
                    __floats2half2_rn(c[fm][fn][0], c[fm][fn][1]);
            if (!guard || r0 + 8 < M)
                *reinterpret_cast<__half2*>(C + (size_t)(r0 + 8) * N + col) =
                    __floats2half2_rn(c[fm][fn][2], c[fm][fn][3]);
        }
    }
}

// ---------------------------------------------------------------------------
// O-projection GEMM (fp32 out + bias, M%128==0, K=INNER_ compile-time).
// ---------------------------------------------------------------------------
__global__ __launch_bounds__(256, 2)
void o_gemm_pipe(const __half* __restrict__ A, const __half* __restrict__ BT,
                 float* __restrict__ C, const float* __restrict__ bias)
{
    extern __shared__ __align__(1024) char dsm[];
    const uint32_t smem_base = smem_u32(dsm);

    const int tid  = threadIdx.x;
    const int wid  = tid >> 5;
    const int lane = tid & 31;
    const int warp_m = wid >> 2;
    const int warp_n = wid & 3;
    const int m0 = blockIdx.y * 128;
    const int n0 = blockIdx.x * 128;
    const int N = QD_;

    float c[4][4][4];
    #pragma unroll
    for (int i = 0; i < 4; i++)
        #pragma unroll
        for (int j = 0; j < 4; j++)
            #pragma unroll
            for (int r = 0; r < 4; r++) c[i][j][r] = 0.f;

    const int lrow = lane & 15;
    const int lchk = lane >> 4;

    gemm_core<INNER_, false>(A, BT, c, smem_base, m0, n0, B_ * NP_, tid,
                             warp_m, warp_n, lrow, lchk);

    float bx[4], by_[4];
    #pragma unroll
    for (int fn = 0; fn < 4; fn++) {
        const int col = n0 + warp_n * 32 + fn * 8 + (lane & 3) * 2;
        bx[fn] = bias[col];
        by_[fn] = bias[col + 1];
    }

    #pragma unroll
    for (int fm = 0; fm < 4; fm++) {
        const int r0 = m0 + warp_m * 64 + fm * 16 + (lane >> 2);
        #pragma unroll
        for (int fn = 0; fn < 4; fn++) {
            const int col = n0 + warp_n * 32 + fn * 8 + (lane & 3) * 2;
            *reinterpret_cast<float2*>(C + (size_t)r0 * N + col) =
                make_float2(c[fm][fn][0] + bx[fn], c[fm][fn][1] + by_[fn]);
            *reinterpret_cast<float2*>(C + (size_t)(r0 + 8) * N + col) =
                make_float2(c[fm][fn][2] + bx[fn], c[fm][fn][3] + by_[fn]);
        }
    }
}

// ---------------------------------------------------------------------------
// Tensor-core flash attention: 128 threads / 64 q-rows per CTA.
// Per-thread code identical to the R12 version (same regs), but the smaller
// CTA (~32KB smem, ~21K regs) reaches ~3 CTAs/SM instead of 1, overlapping
// load/transpose phases of one CTA with MMA phases of others.
// ---------------------------------------------------------------------------
#define NTP 80
#define QS_PITCH 72
#define VT_PITCH 88
#define FQ 64          // q rows per CTA

__global__ __launch_bounds__(128)
void fattn_kernel(const __half* __restrict__ Qh, const __half* __restrict__ Kh,
                  const __half* __restrict__ Vh, const uint32_t* __restrict__ mbits,
                  __half* __restrict__ Oh)
{
    __shared__ __half Qs[FQ * QS_PITCH];
    __shared__ __half Ks[NTP * QS_PITCH];
    __shared__ __half Vt[DH_ * VT_PITCH];

    const int b = blockIdx.z;
    const int h = blockIdx.y;
    const int q0 = blockIdx.x * FQ;
    const int tid = threadIdx.x;
    const int wid = tid >> 5;       // 0..3
    const int lane = tid & 31;

    const uint32_t qs = smem_u32(Qs);
    const uint32_t ks = smem_u32(Ks);
    const uint32_t vt = smem_u32(Vt);

    // Q tile: 64 rows x 8 chunks = 512 cp.async over 128 threads
    #pragma unroll
    for (int t = 0; t < 4; t++) {
        const int idx = tid + t * 128;
        const int row = idx >> 3, cc = idx & 7;
        CP_ASYNC16(qs + (row * QS_PITCH + cc * 8) * 2,
                   Qh + ((size_t)(b * NP_ + q0 + row)) * INNER_ + h * DH_ + cc * 8);
    }
    // K tile: 77 rows x 8 chunks
    for (int idx = tid; idx < NT_ * 8; idx += 128) {
        const int row = idx >> 3, cc = idx & 7;
        CP_ASYNC16(ks + (row * QS_PITCH + cc * 8) * 2,
                   Kh + ((size_t)(b * NT_ + row)) * INNER_ + h * DH_ + cc * 8);
    }
    CP_COMMIT();

    for (int i = tid; i < 3 * QS_PITCH; i += 128)
        Ks[NT_ * QS_PITCH + i] = __float2half(0.f);
    for (int i = tid; i < DH_ * VT_PITCH / 2; i += 128)
        reinterpret_cast<__half2*>(Vt)[i] = __half2(__float2half(0.f), __float2half(0.f));
    __syncthreads();

    for (int idx = tid; idx < NT_ * DH_; idx += 128) {
        const int t = idx >> 6, d = idx & 63;
        Vt[d * VT_PITCH + t] = Vh[((size_t)(b * NT_ + t)) * INNER_ + h * DH_ + d];
    }
    CP_WAIT0();
    __syncthreads();

    const int lrow = lane & 15;
    const int lchk = lane >> 4;

    float s[10][4];
    #pragma unroll
    for (int f = 0; f < 10; f++)
        #pragma unroll
        for (int r = 0; r < 4; r++) s[f][r] = 0.f;

    #pragma unroll
    for (int kstep = 0; kstep < 4; kstep++) {
        const int kc = kstep * 2;
        uint32_t a0, a1, a2, a3;
        LDSM_X4(a0, a1, a2, a3,
                qs + ((wid * 16 + lrow) * QS_PITCH + (kc + lchk) * 8) * 2);
        #pragma unroll
        for (int g = 0; g < 5; g++) {
            uint32_t r0, r1, r2, r3;
            LDSM_X4(r0, r1, r2, r3,
                    ks + ((g * 16 + lrow) * QS_PITCH + (kc + lchk) * 8) * 2);
            MMA_F16(s[2*g+0][0], s[2*g+0][1], s[2*g+0][2], s[2*g+0][3],
                    a0, a1, a2, a3, r0, r2);
            MMA_F16(s[2*g+1][0], s[2*g+1][1], s[2*g+1][2], s[2*g+1][3],
                    a0, a1, a2, a3, r1, r3);
        }
    }

    const int ra = q0 + wid * 16 + (lane >> 2);
    const int rb = ra + 8;
    const uint32_t* bA = mbits + (size_t)(b * NP_ + ra) * 4;
    const uint32_t* bB = mbits + (size_t)(b * NP_ + rb) * 4;
    const uint32_t a0w = bA[0], a1w = bA[1], a2w = bA[2];
    const uint32_t b0w = bB[0], b1w = bB[1], b2w = bB[2];

    float suma = 0.f, sumb = 0.f;
    #pragma unroll
    for (int f = 0; f < 10; f++) {
        const int t0 = f * 8 + (lane & 3) * 2;
        const uint32_t wa = (f < 4) ? a0w : (f < 8) ? a1w : a2w;
        const uint32_t wb = (f < 4) ? b0w : (f < 8) ? b1w : b2w;
        const int sh = t0 & 31;
        float e0 = ((wa >> sh) & 1)       ? __expf(s[f][0] * 0.125f) : 0.f;
        float e1 = ((wa >> (sh + 1)) & 1) ? __expf(s[f][1] * 0.125f) : 0.f;
        float e2 = ((wb >> sh) & 1)       ? __expf(s[f][2] * 0.125f) : 0.f;
        float e3 = ((wb >> (sh + 1)) & 1) ? __expf(s[f][3] * 0.125f) : 0.f;
        s[f][0] = e0; s[f][1] = e1; s[f][2] = e2; s[f][3] = e3;
        suma += e0 + e1;
        sumb += e2 + e3;
    }
    suma += __shfl_xor_sync(0xFFFFFFFF, suma, 1);
    suma += __shfl_xor_sync(0xFFFFFFFF, suma, 2);
    sumb += __shfl_xor_sync(0xFFFFFFFF, sumb, 1);
    sumb += __shfl_xor_sync(0xFFFFFFFF, sumb, 2);
    const float inva = 1.f / suma;
    const float invb = 1.f / sumb;

    uint32_t p[5][4];
    #pragma unroll
    for (int kstep = 0; kstep < 5; kstep++) {
        const int f0 = 2 * kstep, f1 = 2 * kstep + 1;
        p[kstep][0] = packh2(s[f0][0], s[f0][1]);
        p[kstep][1] = packh2(s[f0][2], s[f0][3]);
        p[kstep][2] = packh2(s[f1][0], s[f1][1]);
        p[kstep][3] = packh2(s[f1][2], s[f1][3]);
    }

    float o[8][4];
    #pragma unroll
    for (int f = 0; f < 8; f++)
        #pragma unroll
        for (int r = 0; r < 4; r++) o[f][r] = 0.f;

    #pragma unroll
    for (int kstep = 0; kstep < 5; kstep++) {
        const int tc = kstep * 2;
        #pragma unroll
        for (int g = 0; g < 4; g++) {
            uint32_t r0, r1, r2, r3;
            LDSM_X4(r0, r1, r2, r3,
                    vt + ((g * 16 + lrow) * VT_PITCH + (tc + lchk) * 8) * 2);
            MMA_F16(o[2*g+0][0], o[2*g+0][1], o[2*g+0][2], o[2*g+0][3],
                    p[kstep][0], p[kstep][1], p[kstep][2], p[kstep][3], r0, r2);
            MMA_F16(o[2*g+1][0], o[2*g+1][1], o[2*g+1][2], o[2*g+1][3],
                    p[kstep][0], p[kstep][1], p[kstep][2], p[kstep][3], r1, r3);
        }
    }

    __half* outA = Oh + ((size_t)(b * NP_ + ra)) * INNER_ + h * DH_;
    __half* outB = Oh + ((size_t)(b * NP_ + rb)) * INNER_ + h * DH_;
    #pragma unroll
    for (int f = 0; f < 8; f++) {
        const int d = f * 8 + (lane & 3) * 2;
        *reinterpret_cast<__half2*>(outA + d) =
            __floats2half2_rn(o[f][0] * inva, o[f][1] * inva);
        *reinterpret_cast<__half2*>(outB + d) =
            __floats2half2_rn(o[f][2] * invb, o[f][3] * invb);
    }
}

// ---------------------------------------------------------------------------
// Launch: 4 kernels total.
// ---------------------------------------------------------------------------
extern "C" void kernel_launch(void* const* d_in, const int* in_sizes, int n_in,
                              void* d_out, int out_size)
{
    const float* x    = (const float*)d_in[0];
    const float* ctx  = (const float*)d_in[1];
    const int*   mask = (const int*)  d_in[2];
    const float* Wq   = (const float*)d_in[3];
    const float* Wk   = (const float*)d_in[4];
    const float* Wv   = (const float*)d_in[5];
    const float* Wo   = (const float*)d_in[6];
    const float* bo   = (const float*)d_in[7];
    float* out = (float*)d_out;

    __half *Qh, *Kh, *Vh, *xh, *ah, *ch, *wqt, *wkt, *wvt, *wot;
    uint32_t* mb;
    cudaGetSymbolAddress((void**)&Qh,  g_Qh);
    cudaGetSymbolAddress((void**)&Kh,  g_Kh);
    cudaGetSymbolAddress((void**)&Vh,  g_Vh);
    cudaGetSymbolAddress((void**)&xh,  g_xh);
    cudaGetSymbolAddress((void**)&ah,  g_ah);
    cudaGetSymbolAddress((void**)&ch,  g_ch);
    cudaGetSymbolAddress((void**)&wqt, g_WqT);
    cudaGetSymbolAddress((void**)&wkt, g_WkT);
    cudaGetSymbolAddress((void**)&wvt, g_WvT);
    cudaGetSymbolAddress((void**)&wot, g_WoT);
    cudaGetSymbolAddress((void**)&mb,  g_mb);

    cudaFuncSetAttribute(qkv_gemm_pipe,
                         cudaFuncAttributeMaxDynamicSharedMemorySize, PIPE_SMEM);
    cudaFuncSetAttribute(o_gemm_pipe,
                         cudaFuncAttributeMaxDynamicSharedMemorySize, PIPE_SMEM);

    const int Mq = B_ * NP_;   // 65536

    // 1) all conversions + mask bits, one launch
    prep_kernel<<<PREP_BLOCKS, 256>>>(x, ctx, mask, Wq, Wk, Wv, Wo,
                                      xh, ch, wqt, wkt, wvt, wot, mb);

    // 2) Q + K + V projections, one launch (Q branch first: hot path first)
    qkv_gemm_pipe<<<dim3(INNER_ / 128, QY + 2 * KVY, 1), 256, PIPE_SMEM>>>(
        xh, wqt, Qh, ch, wkt, Kh, wvt, Vh);

    // 3) tensor-core flash attention -> fp16 (64 q-rows per 128-thread CTA)
    fattn_kernel<<<dim3(NP_ / FQ, H_, B_), 128>>>(Qh, Kh, Vh, mb, ah);

    // 4) out = Att @ Wo + bo
    o_gemm_pipe<<<dim3(QD_ / 128, Mq / 128, 1), 256, PIPE_SMEM>>>(
        ah, wot, out, bo);
}

// round 17
// speedup vs baseline: 1.6066x; 1.0589x over previous
#include <cuda_runtime.h>
#include <cuda_fp16.h>
#include <cstdint>

// Problem constants
#define B_   16
#define NP_  4096
#define NT_  77
#define QD_  512
#define CD_  768
#define H_   8
#define DH_  64
#define INNER_ 512   // H*DH

// ---------------------------------------------------------------------------
// Scratch (device globals)
// ---------------------------------------------------------------------------
__device__ __half    g_Qh [(size_t)B_ * NP_ * INNER_];
__device__ __half    g_Kh [(size_t)B_ * NT_ * INNER_];
__device__ __half    g_Vh [(size_t)B_ * NT_ * INNER_];
__device__ __half    g_xh [(size_t)B_ * NP_ * QD_];
__device__ __half    g_ah [(size_t)B_ * NP_ * INNER_];
__device__ __half    g_ch [(size_t)B_ * NT_ * CD_];
__device__ __half    g_WqT[(size_t)QD_ * INNER_];
__device__ __half    g_WkT[(size_t)CD_ * INNER_];
__device__ __half    g_WvT[(size_t)CD_ * INNER_];
__device__ __half    g_WoT[(size_t)INNER_ * QD_];
__device__ uint32_t  g_mb [(size_t)B_ * NP_ * 4];

// ---------------------------------------------------------------------------
// PTX helpers
// ---------------------------------------------------------------------------
__device__ __forceinline__ uint32_t smem_u32(const void* p) {
    uint32_t a;
    asm("{ .reg .u64 t; cvta.to.shared.u64 t, %1; cvt.u32.u64 %0, t; }" : "=r"(a) : "l"(p));
    return a;
}

#define LDSM_X4(r0, r1, r2, r3, addr) \
    asm volatile("ldmatrix.sync.aligned.m8n8.x4.shared.b16 {%0,%1,%2,%3}, [%4];" \
        : "=r"(r0), "=r"(r1), "=r"(r2), "=r"(r3) : "r"(addr))

#define MMA_F16(c0, c1, c2, c3, a0, a1, a2, a3, b0, b1) \
    asm volatile("mma.sync.aligned.m16n8k16.row.col.f32.f16.f16.f32 " \
        "{%0,%1,%2,%3}, {%4,%5,%6,%7}, {%8,%9}, {%0,%1,%2,%3};" \
        : "+f"(c0), "+f"(c1), "+f"(c2), "+f"(c3) \
        : "r"(a0), "r"(a1), "r"(a2), "r"(a3), "r"(b0), "r"(b1))

#define CP_ASYNC16(dst, src) \
    asm volatile("cp.async.cg.shared.global [%0], [%1], 16;" :: "r"(dst), "l"(src))
#define CP_COMMIT() asm volatile("cp.async.commit_group;" ::: "memory")
#define CP_WAIT1()  asm volatile("cp.async.wait_group 1;" ::: "memory")
#define CP_WAIT0()  asm volatile("cp.async.wait_group 0;" ::: "memory")

// BK=64 smem tile: rows of 64 halves (128B); 16B chunks XOR-swizzled.
__device__ __forceinline__ uint32_t tile_off64(int row, int chunk) {
    return (uint32_t)(row * 128 + ((chunk ^ (row & 7)) << 4));
}

__device__ __forceinline__ uint32_t packh2(float x, float y) {
    __half2 h = __floats2half2_rn(x, y);
    return *reinterpret_cast<uint32_t*>(&h);
}

// ---------------------------------------------------------------------------
// Mega prep kernel; tohalf now 2 float4 per thread (MLP=2).
// ---------------------------------------------------------------------------
#define PX_N4   ((B_ * NP_ * QD_) / 4)          // 8388608
#define PC_N4   ((B_ * NT_ * CD_) / 4)          // 236544
#define PX_BLK  (PX_N4 / 512)                   // 16384
#define PC_BLK  (PC_N4 / 512)                   // 462
#define WQ_BLK  ((QD_ / 32) * (INNER_ / 32))
#define WK_BLK  ((CD_ / 32) * (INNER_ / 32))
#define WV_BLK  WK_BLK
#define WO_BLK  ((INNER_ / 32) * (QD_ / 32))
#define MB_BLK  ((B_ * NP_) / 8)

#define E_X   PX_BLK
#define E_C   (E_X + PC_BLK)
#define E_WQ  (E_C + WQ_BLK)
#define E_WK  (E_WQ + WK_BLK)
#define E_WV  (E_WK + WV_BLK)
#define E_WO  (E_WV + WO_BLK)
#define E_MB  (E_WO + MB_BLK)
#define PREP_BLOCKS E_MB

__device__ __forceinline__ void tohalf_sub2(const float4* in, __half2* out, int base)
{
    const int i0 = base;
    const int i1 = base + 256;
    float4 v0 = in[i0];
    float4 v1 = in[i1];
    out[2 * i0]     = __floats2half2_rn(v0.x, v0.y);
    out[2 * i0 + 1] = __floats2half2_rn(v0.z, v0.w);
    out[2 * i1]     = __floats2half2_rn(v1.x, v1.y);
    out[2 * i1 + 1] = __floats2half2_rn(v1.z, v1.w);
}

__device__ __forceinline__ void transT_sub(const float* in, __half* out,
                                           int K, int N, int t, int tid,
                                           float (*tsm)[33])
{
    const int ktiles = K / 32;
    const int kb = (t % ktiles) * 32;
    const int nb = (t / ktiles) * 32;
    const int tx = tid & 31;
    const int ty = tid >> 5;
    #pragma unroll
    for (int i = 0; i < 32; i += 8)
        tsm[ty + i][tx] = in[(size_t)(kb + ty + i) * N + nb + tx];
    __syncthreads();
    #pragma unroll
    for (int i = 0; i < 32; i += 8)
        out[(size_t)(nb + ty + i) * K + kb + tx] = __float2half_rn(tsm[tx][ty + i]);
}

__global__ __launch_bounds__(256)
void prep_kernel(const float* __restrict__ x, const float* __restrict__ ctx,
                 const int* __restrict__ mask,
                 const float* __restrict__ Wq, const float* __restrict__ Wk,
                 const float* __restrict__ Wv, const float* __restrict__ Wo,
                 __half* __restrict__ xh, __half* __restrict__ ch,
                 __half* __restrict__ wqt, __half* __restrict__ wkt,
                 __half* __restrict__ wvt, __half* __restrict__ wot,
                 uint32_t* __restrict__ mbits)
{
    __shared__ float tsm[32][33];
    const int bid = blockIdx.x;
    const int tid = threadIdx.x;

    if (bid < E_X) {
        tohalf_sub2((const float4*)x, (__half2*)xh, bid * 512 + tid);
    } else if (bid < E_C) {
        tohalf_sub2((const float4*)ctx, (__half2*)ch, (bid - E_X) * 512 + tid);
    } else if (bid < E_WQ) {
        transT_sub(Wq, wqt, QD_, INNER_, bid - E_C, tid, tsm);
    } else if (bid < E_WK) {
        transT_sub(Wk, wkt, CD_, INNER_, bid - E_WQ, tid, tsm);
    } else if (bid < E_WV) {
        transT_sub(Wv, wvt, CD_, INNER_, bid - E_WK, tid, tsm);
    } else if (bid < E_WO) {
        transT_sub(Wo, wot, INNER_, QD_, bid - E_WV, tid, tsm);
    } else {
        const int w = (bid - E_WO) * 8 + (tid >> 5);
        const int lane = tid & 31;
        const int* row = mask + (size_t)w * NT_;
        uint32_t b0 = __ballot_sync(0xFFFFFFFF, row[lane] != 0);
        uint32_t b1 = __ballot_sync(0xFFFFFFFF, row[32 + lane] != 0);
        uint32_t b2 = __ballot_sync(0xFFFFFFFF, (64 + lane < NT_) ? (row[64 + lane] != 0) : 0);
        if (lane == 0) {
            mbits[(size_t)w * 4 + 0] = b0;
            mbits[(size_t)w * 4 + 1] = b1;
            mbits[(size_t)w * 4 + 2] = b2;
            mbits[(size_t)w * 4 + 3] = 0;
        }
    }
}

// ---------------------------------------------------------------------------
// GEMM core (stable R12 operating point: 128x128 CTA, 8 warps of 64x32,
// BK=64, 3-stage cp.async, occ 2, KVAL compile-time -> full unroll).
// ---------------------------------------------------------------------------
#define STG_A 0
#define STG_B 16384
#define STG_SIZE 32768
#define NSTAGE 3
#define PIPE_SMEM (NSTAGE * STG_SIZE)   // 98304

#define QY 512
#define KVY 10

template<int KVAL, bool GUARD>
__device__ __forceinline__ void gemm_core(
    const __half* __restrict__ A, const __half* __restrict__ BT,
    float c[4][4][4], uint32_t smem_base,
    int m0, int n0, int M, int tid,
    int warp_m, int warp_n, int lrow, int lchk)
{
    constexpr int NCH = KVAL >> 6;

    auto load_chunk = [&](int s, int k0) {
        const uint32_t sb = smem_base + s * STG_SIZE;
        #pragma unroll
        for (int t = 0; t < 4; t++) {
            const int idx = tid + t * 256;
            const int row = idx >> 3, cc = idx & 7;
            const int ar = GUARD ? min(m0 + row, M - 1) : (m0 + row);
            CP_ASYNC16(sb + STG_A + tile_off64(row, cc),
                       A + (size_t)ar * KVAL + k0 + cc * 8);
        }
        #pragma unroll
        for (int t = 0; t < 4; t++) {
            const int idx = tid + t * 256;
            const int row = idx >> 3, cc = idx & 7;
            CP_ASYNC16(sb + STG_B + tile_off64(row, cc),
                       BT + (size_t)(n0 + row) * KVAL + k0 + cc * 8);
        }
        CP_COMMIT();
    };

    load_chunk(0, 0);
    load_chunk(1, 64);

    #pragma unroll
    for (int ch_ = 0; ch_ < NCH; ch_++) {
        if (ch_ + 1 < NCH) CP_WAIT1(); else CP_WAIT0();
        __syncthreads();

        if (ch_ + 2 < NCH)
            load_chunk((ch_ + 2) % NSTAGE, (ch_ + 2) << 6);

        const uint32_t sb = smem_base + (ch_ % NSTAGE) * STG_SIZE;

        #pragma unroll
        for (int ks = 0; ks < 4; ks++) {
            const int kc = ks * 2;
            uint32_t b[4][2];
            #pragma unroll
            for (int fp = 0; fp < 2; fp++) {
                const int row = warp_n * 32 + fp * 16 + lrow;
                uint32_t r0, r1, r2, r3;
                LDSM_X4(r0, r1, r2, r3, sb + STG_B + tile_off64(row, kc + lchk));
                b[2 * fp + 0][0] = r0; b[2 * fp + 0][1] = r2;
                b[2 * fp + 1][0] = r1; b[2 * fp + 1][1] = r3;
            }
            #pragma unroll
            for (int fm = 0; fm < 4; fm++) {
                const int row = warp_m * 64 + fm * 16 + lrow;
                uint32_t a0, a1, a2, a3;
                LDSM_X4(a0, a1, a2, a3, sb + STG_A + tile_off64(row, kc + lchk));
                #pragma unroll
                for (int fn = 0; fn < 4; fn++)
                    MMA_F16(c[fm][fn][0], c[fm][fn][1], c[fm][fn][2], c[fm][fn][3],
                            a0, a1, a2, a3, b[fn][0], b[fn][1]);
            }
        }
    }
}

// ---------------------------------------------------------------------------
// Merged Q/K/V projection GEMM (Q branch first: hot path first in binary).
// ---------------------------------------------------------------------------
__global__ __launch_bounds__(256, 2)
void qkv_gemm_pipe(const __half* __restrict__ xh, const __half* __restrict__ wqt,
                   __half* __restrict__ Qh,
                   const __half* __restrict__ ch, const __half* __restrict__ wkt,
                   __half* __restrict__ Kh, const __half* __restrict__ wvt,
                   __half* __restrict__ Vh)
{
    extern __shared__ __align__(1024) char dsm[];
    const uint32_t smem_base = smem_u32(dsm);

    const int by = blockIdx.y;
    const int tid  = threadIdx.x;
    const int wid  = tid >> 5;
    const int lane = tid & 31;
    const int warp_m = wid >> 2;
    const int warp_n = wid & 3;
    const int n0 = blockIdx.x * 128;
    const int N = INNER_;

    float c[4][4][4];
    #pragma unroll
    for (int i = 0; i < 4; i++)
        #pragma unroll
        for (int j = 0; j < 4; j++)
            #pragma unroll
            for (int r = 0; r < 4; r++) c[i][j][r] = 0.f;

    const int lrow = lane & 15;
    const int lchk = lane >> 4;

    __half* C;
    int M, m0;
    bool guard;
    if (by < QY) {
        M = B_ * NP_; m0 = by * 128; C = Qh; guard = false;
        gemm_core<QD_, false>(xh, wqt, c, smem_base, m0, n0, M, tid,
                              warp_m, warp_n, lrow, lchk);
    } else {
        M = B_ * NT_;
        const __half* BT;
        if (by < QY + KVY) { m0 = (by - QY) * 128; BT = wkt; C = Kh; }
        else               { m0 = (by - QY - KVY) * 128; BT = wvt; C = Vh; }
        guard = true;
        gemm_core<CD_, true>(ch, BT, c, smem_base, m0, n0, M, tid,
                             warp_m, warp_n, lrow, lchk);
    }

    #pragma unroll
    for (int fm = 0; fm < 4; fm++) {
        const int r0 = m0 + warp_m * 64 + fm * 16 + (lane >> 2);
        #pragma unroll
        for (int fn = 0; fn < 4; fn++) {
            const int col = n0 + warp_n * 32 + fn * 8 + (lane & 3) * 2;
            if (!guard || r0 < M)
                *reinterpret_cast<__half2*>(C + (size_t)r0 * N + col) =
                    __floats2half2_rn(c[fm][fn][0], c[fm][fn][1]);
            if (!guard || r0 + 8 < M)
                *reinterpret_cast<__half2*>(C + (size_t)(r0 + 8) * N + col) =
                    __floats2half2_rn(c[fm][fn][2], c[fm][fn][3]);
        }
    }
}

// ---------------------------------------------------------------------------
// O-projection GEMM (fp32 out + bias, M%128==0, K=INNER_ compile-time).
// ---------------------------------------------------------------------------
__global__ __launch_bounds__(256, 2)
void o_gemm_pipe(const __half* __restrict__ A, const __half* __restrict__ BT,
                 float* __restrict__ C, const float* __restrict__ bias)
{
    extern __shared__ __align__(1024) char dsm[];
    const uint32_t smem_base = smem_u32(dsm);

    const int tid  = threadIdx.x;
    const int wid  = tid >> 5;
    const int lane = tid & 31;
    const int warp_m = wid >> 2;
    const int warp_n = wid & 3;
    const int m0 = blockIdx.y * 128;
    const int n0 = blockIdx.x * 128;
    const int N = QD_;

    float c[4][4][4];
    #pragma unroll
    for (int i = 0; i < 4; i++)
        #pragma unroll
        for (int j = 0; j < 4; j++)
            #pragma unroll
            for (int r = 0; r < 4; r++) c[i][j][r] = 0.f;

    const int lrow = lane & 15;
    const int lchk = lane >> 4;

    gemm_core<INNER_, false>(A, BT, c, smem_base, m0, n0, B_ * NP_, tid,
                             warp_m, warp_n, lrow, lchk);

    float bx[4], by_[4];
    #pragma unroll
    for (int fn = 0; fn < 4; fn++) {
        const int col = n0 + warp_n * 32 + fn * 8 + (lane & 3) * 2;
        bx[fn] = bias[col];
        by_[fn] = bias[col + 1];
    }

    #pragma unroll
    for (int fm = 0; fm < 4; fm++) {
        const int r0 = m0 + warp_m * 64 + fm * 16 + (lane >> 2);
        #pragma unroll
        for (int fn = 0; fn < 4; fn++) {
            const int col = n0 + warp_n * 32 + fn * 8 + (lane & 3) * 2;
            *reinterpret_cast<float2*>(C + (size_t)r0 * N + col) =
                make_float2(c[fm][fn][0] + bx[fn], c[fm][fn][1] + by_[fn]);
            *reinterpret_cast<float2*>(C + (size_t)(r0 + 8) * N + col) =
                make_float2(c[fm][fn][2] + bx[fn], c[fm][fn][3] + by_[fn]);
        }
    }
}

// ---------------------------------------------------------------------------
// Tensor-core flash attention: 128 threads / 64 q-rows per CTA (~3 CTAs/SM).
// V is now staged row-major via cp.async and transposed smem->smem
// (replaces the scalar 2-byte global-load transpose: ~16x sector inflation).
// ---------------------------------------------------------------------------
#define NTP 80
#define QS_PITCH 72
#define VT_PITCH 88
#define FQ 64          // q rows per CTA

__global__ __launch_bounds__(128)
void fattn_kernel(const __half* __restrict__ Qh, const __half* __restrict__ Kh,
                  const __half* __restrict__ Vh, const uint32_t* __restrict__ mbits,
                  __half* __restrict__ Oh)
{
    __shared__ __half Qs[FQ * QS_PITCH];
    __shared__ __half Ks[NTP * QS_PITCH];
    __shared__ __half Vs[NT_ * QS_PITCH];   // V staging, row-major
    __shared__ __half Vt[DH_ * VT_PITCH];   // V transposed

    const int b = blockIdx.z;
    const int h = blockIdx.y;
    const int q0 = blockIdx.x * FQ;
    const int tid = threadIdx.x;
    const int wid = tid >> 5;       // 0..3
    const int lane = tid & 31;

    const uint32_t qs = smem_u32(Qs);
    const uint32_t ks = smem_u32(Ks);
    const uint32_t vs = smem_u32(Vs);
    const uint32_t vt = smem_u32(Vt);

    // Q tile: 64 rows x 8 chunks = 512 cp.async
    #pragma unroll
    for (int t = 0; t < 4; t++) {
        const int idx = tid + t * 128;
        const int row = idx >> 3, cc = idx & 7;
        CP_ASYNC16(qs + (row * QS_PITCH + cc * 8) * 2,
                   Qh + ((size_t)(b * NP_ + q0 + row)) * INNER_ + h * DH_ + cc * 8);
    }
    // K tile + V staging: 77 rows x 8 chunks each
    for (int idx = tid; idx < NT_ * 8; idx += 128) {
        const int row = idx >> 3, cc = idx & 7;
        const size_t src = ((size_t)(b * NT_ + row)) * INNER_ + h * DH_ + cc * 8;
        CP_ASYNC16(ks + (row * QS_PITCH + cc * 8) * 2, Kh + src);
        CP_ASYNC16(vs + (row * QS_PITCH + cc * 8) * 2, Vh + src);
    }
    CP_COMMIT();

    // zero K pad rows and all of Vt (independent of async copies)
    for (int i = tid; i < 3 * QS_PITCH; i += 128)
        Ks[NT_ * QS_PITCH + i] = __float2half(0.f);
    for (int i = tid; i < DH_ * VT_PITCH / 2; i += 128)
        reinterpret_cast<__half2*>(Vt)[i] = __half2(__float2half(0.f), __float2half(0.f));

    CP_WAIT0();
    __syncthreads();   // all async copies + zeros visible

    // transpose V: smem -> smem
    for (int idx = tid; idx < NT_ * DH_; idx += 128) {
        const int t = idx >> 6, d = idx & 63;
        Vt[d * VT_PITCH + t] = Vs[t * QS_PITCH + d];
    }
    __syncthreads();

    const int lrow = lane & 15;
    const int lchk = lane >> 4;

    float s[10][4];
    #pragma unroll
    for (int f = 0; f < 10; f++)
        #pragma unroll
        for (int r = 0; r < 4; r++) s[f][r] = 0.f;

    #pragma unroll
    for (int kstep = 0; kstep < 4; kstep++) {
        const int kc = kstep * 2;
        uint32_t a0, a1, a2, a3;
        LDSM_X4(a0, a1, a2, a3,
                qs + ((wid * 16 + lrow) * QS_PITCH + (kc + lchk) * 8) * 2);
        #pragma unroll
        for (int g = 0; g < 5; g++) {
            uint32_t r0, r1, r2, r3;
            LDSM_X4(r0, r1, r2, r3,
                    ks + ((g * 16 + lrow) * QS_PITCH + (kc + lchk) * 8) * 2);
            MMA_F16(s[2*g+0][0], s[2*g+0][1], s[2*g+0][2], s[2*g+0][3],
                    a0, a1, a2, a3, r0, r2);
            MMA_F16(s[2*g+1][0], s[2*g+1][1], s[2*g+1][2], s[2*g+1][3],
                    a0, a1, a2, a3, r1, r3);
        }
    }

    const int ra = q0 + wid * 16 + (lane >> 2);
    const int rb = ra + 8;
    const uint32_t* bA = mbits + (size_t)(b * NP_ + ra) * 4;
    const uint32_t* bB = mbits + (size_t)(b * NP_ + rb) * 4;
    const uint32_t a0w = bA[0], a1w = bA[1], a2w = bA[2];
    const uint32_t b0w = bB[0], b1w = bB[1], b2w = bB[2];

    float suma = 0.f, sumb = 0.f;
    #pragma unroll
    for (int f = 0; f < 10; f++) {
        const int t0 = f * 8 + (lane & 3) * 2;
        const uint32_t wa = (f < 4) ? a0w : (f < 8) ? a1w : a2w;
        const uint32_t wb = (f < 4) ? b0w : (f < 8) ? b1w : b2w;
        const int sh = t0 & 31;
        float e0 = ((wa >> sh) & 1)       ? __expf(s[f][0] * 0.125f) : 0.f;
        float e1 = ((wa >> (sh + 1)) & 1) ? __expf(s[f][1] * 0.125f) : 0.f;
        float e2 = ((wb >> sh) & 1)       ? __expf(s[f][2] * 0.125f) : 0.f;
        float e3 = ((wb >> (sh + 1)) & 1) ? __expf(s[f][3] * 0.125f) : 0.f;
        s[f][0] = e0; s[f][1] = e1; s[f][2] = e2; s[f][3] = e3;
        suma += e0 + e1;
        sumb += e2 + e3;
    }
    suma += __shfl_xor_sync(0xFFFFFFFF, suma, 1);
    suma += __shfl_xor_sync(0xFFFFFFFF, suma, 2);
    sumb += __shfl_xor_sync(0xFFFFFFFF, sumb, 1);
    sumb += __shfl_xor_sync(0xFFFFFFFF, sumb, 2);
    const float inva = 1.f / suma;
    const float invb = 1.f / sumb;

    uint32_t p[5][4];
    #pragma unroll
    for (int kstep = 0; kstep < 5; kstep++) {
        const int f0 = 2 * kstep, f1 = 2 * kstep + 1;
        p[kstep][0] = packh2(s[f0][0], s[f0][1]);
        p[kstep][1] = packh2(s[f0][2], s[f0][3]);
        p[kstep][2] = packh2(s[f1][0], s[f1][1]);
        p[kstep][3] = packh2(s[f1][2], s[f1][3]);
    }

    float o[8][4];
    #pragma unroll
    for (int f = 0; f < 8; f++)
        #pragma unroll
        for (int r = 0; r < 4; r++) o[f][r] = 0.f;

    #pragma unroll
    for (int kstep = 0; kstep < 5; kstep++) {
        const int tc = kstep * 2;
        #pragma unroll
        for (int g = 0; g < 4; g++) {
            uint32_t r0, r1, r2, r3;
            LDSM_X4(r0, r1, r2, r3,
                    vt + ((g * 16 + lrow) * VT_PITCH + (tc + lchk) * 8) * 2);
            MMA_F16(o[2*g+0][0], o[2*g+0][1], o[2*g+0][2], o[2*g+0][3],
                    p[kstep][0], p[kstep][1], p[kstep][2], p[kstep][3], r0, r2);
            MMA_F16(o[2*g+1][0], o[2*g+1][1], o[2*g+1][2], o[2*g+1][3],
                    p[kstep][0], p[kstep][1], p[kstep][2], p[kstep][3], r1, r3);
        }
    }

    __half* outA = Oh + ((size_t)(b * NP_ + ra)) * INNER_ + h * DH_;
    __half* outB = Oh + ((size_t)(b * NP_ + rb)) * INNER_ + h * DH_;
    #pragma unroll
    for (int f = 0; f < 8; f++) {
        const int d = f * 8 + (lane & 3) * 2;
        *reinterpret_cast<__half2*>(outA + d) =
            __floats2half2_rn(o[f][0] * inva, o[f][1] * inva);
        *reinterpret_cast<__half2*>(outB + d) =
            __floats2half2_rn(o[f][2] * invb, o[f][3] * invb);
    }
}

// ---------------------------------------------------------------------------
// Launch: 4 kernels total.
// ---------------------------------------------------------------------------
extern "C" void kernel_launch(void* const* d_in, const int* in_sizes, int n_in,
                              void* d_out, int out_size)
{
    const float* x    = (const float*)d_in[0];
    const float* ctx  = (const float*)d_in[1];
    const int*   mask = (const int*)  d_in[2];
    const float* Wq   = (const float*)d_in[3];
    const float* Wk   = (const float*)d_in[4];
    const float* Wv   = (const float*)d_in[5];
    const float* Wo   = (const float*)d_in[6];
    const float* bo   = (const float*)d_in[7];
    float* out = (float*)d_out;

    __half *Qh, *Kh, *Vh, *xh, *ah, *ch, *wqt, *wkt, *wvt, *wot;
    uint32_t* mb;
    cudaGetSymbolAddress((void**)&Qh,  g_Qh);
    cudaGetSymbolAddress((void**)&Kh,  g_Kh);
    cudaGetSymbolAddress((void**)&Vh,  g_Vh);
    cudaGetSymbolAddress((void**)&xh,  g_xh);
    cudaGetSymbolAddress((void**)&ah,  g_ah);
    cudaGetSymbolAddress((void**)&ch,  g_ch);
    cudaGetSymbolAddress((void**)&wqt, g_WqT);
    cudaGetSymbolAddress((void**)&wkt, g_WkT);
    cudaGetSymbolAddress((void**)&wvt, g_WvT);
    cudaGetSymbolAddress((void**)&wot, g_WoT);
    cudaGetSymbolAddress((void**)&mb,  g_mb);

    cudaFuncSetAttribute(qkv_gemm_pipe,
                         cudaFuncAttributeMaxDynamicSharedMemorySize, PIPE_SMEM);
    cudaFuncSetAttribute(o_gemm_pipe,
                         cudaFuncAttributeMaxDynamicSharedMemorySize, PIPE_SMEM);

    const int Mq = B_ * NP_;   // 65536

    // 1) all conversions + mask bits, one launch
    prep_kernel<<<PREP_BLOCKS, 256>>>(x, ctx, mask, Wq, Wk, Wv, Wo,
                                      xh, ch, wqt, wkt, wvt, wot, mb);

    // 2) Q + K + V projections, one launch
    qkv_gemm_pipe<<<dim3(INNER_ / 128, QY + 2 * KVY, 1), 256, PIPE_SMEM>>>(
        xh, wqt, Qh, ch, wkt, Kh, wvt, Vh);

    // 3) tensor-core flash attention -> fp16
    fattn_kernel<<<dim3(NP_ / FQ, H_, B_), 128>>>(Qh, Kh, Vh, mb, ah);

    // 4) out = Att @ Wo + bo
    o_gemm_pipe<<<dim3(QD_ / 128, Mq / 128, 1), 256, PIPE_SMEM>>>(
        ah, wot, out, bo);
}